// round 11
// baseline (speedup 1.0000x reference)
#include <cuda_runtime.h>
#include <cuda_fp16.h>
#include <math.h>
#include <stdint.h>

#define EMBED  1024
#define NHEADS 16
#define HDIM   64
#define VOCAB  4096
#define BATCH  2
#define SQL    1024
#define SKVL   2048

#define NX_ROWS (BATCH * SQL)    // 2048
#define NC_ROWS (BATCH * SKVL)   // 4096

// ---------------------------------------------------------------------------
// Scratch (allocation-free __device__ globals)
// ---------------------------------------------------------------------------
// int8 hi/lo activations + weights (all K-major rows of length 1024)
__device__ __align__(16) int8_t g_x8h [NX_ROWS * EMBED];
__device__ __align__(16) int8_t g_x8l [NX_ROWS * EMBED];
__device__ __align__(16) int8_t g_c8h [NC_ROWS * EMBED];
__device__ __align__(16) int8_t g_c8l [NC_ROWS * EMBED];
__device__ __align__(16) int8_t g_ao8h[NX_ROWS * EMBED];
__device__ __align__(16) int8_t g_ao8l[NX_ROWS * EMBED];
__device__ __align__(16) int8_t g_wq8h[EMBED * EMBED];
__device__ __align__(16) int8_t g_wq8l[EMBED * EMBED];
__device__ __align__(16) int8_t g_wk8h[EMBED * EMBED];
__device__ __align__(16) int8_t g_wk8l[EMBED * EMBED];
__device__ __align__(16) int8_t g_wv8h[EMBED * EMBED];
__device__ __align__(16) int8_t g_wv8l[EMBED * EMBED];
__device__ __align__(16) int8_t g_wp8h[VOCAB * EMBED];
__device__ __align__(16) int8_t g_wp8l[VOCAB * EMBED];
// per-row scales
__device__ float g_sx [NX_ROWS];
__device__ float g_sc [NC_ROWS];
__device__ float g_sao[NX_ROWS];
__device__ float g_swq[EMBED];
__device__ float g_swk[EMBED];
__device__ float g_swv[EMBED];
__device__ float g_swp[VOCAB];
// fp16 hi/lo Q/K/V for flash
__device__ __align__(16) __half g_Qh[NX_ROWS * EMBED];
__device__ __align__(16) __half g_Ql[NX_ROWS * EMBED];
__device__ __align__(16) __half g_Kh[NC_ROWS * EMBED];
__device__ __align__(16) __half g_Kl[NC_ROWS * EMBED];
__device__ __align__(16) __half g_Vh[NC_ROWS * EMBED];
__device__ __align__(16) __half g_Vl[NC_ROWS * EMBED];
// fp32 attention output + fp32 transpose scratch
__device__ __align__(16) float g_AOf[NX_ROWS * EMBED];
__device__ __align__(16) float g_WtF[VOCAB * EMBED];

// ---------------------------------------------------------------------------
// Helpers
// ---------------------------------------------------------------------------
__device__ __forceinline__ uint32_t smem_u32(const void* p) {
    uint32_t a;
    asm("{ .reg .u64 t; cvta.to.shared.u64 t, %1; cvt.u32.u64 %0, t; }"
        : "=r"(a) : "l"(p));
    return a;
}
__device__ __forceinline__ void cpasync16(uint32_t dst, const void* src) {
    asm volatile("cp.async.cg.shared.global [%0], [%1], 16;"
                 :: "r"(dst), "l"(src) : "memory");
}
#define CP_COMMIT() asm volatile("cp.async.commit_group;" ::: "memory")
#define CP_WAIT(N)  asm volatile("cp.async.wait_group %0;" :: "n"(N) : "memory")

// fp16 in, fp32 accum
__device__ __forceinline__ void mma16816(float* c, const uint32_t* a,
                                         uint32_t b0, uint32_t b1) {
    asm volatile(
        "mma.sync.aligned.m16n8k16.row.col.f32.f16.f16.f32 "
        "{%0,%1,%2,%3}, {%4,%5,%6,%7}, {%8,%9}, {%0,%1,%2,%3};"
        : "+f"(c[0]), "+f"(c[1]), "+f"(c[2]), "+f"(c[3])
        : "r"(a[0]), "r"(a[1]), "r"(a[2]), "r"(a[3]), "r"(b0), "r"(b1));
}
// int8 in, s32 accum, k32
__device__ __forceinline__ void imma16832(int* c, const uint32_t* a,
                                          uint32_t b0, uint32_t b1) {
    asm volatile(
        "mma.sync.aligned.m16n8k32.row.col.s32.s8.s8.s32 "
        "{%0,%1,%2,%3}, {%4,%5,%6,%7}, {%8,%9}, {%0,%1,%2,%3};"
        : "+r"(c[0]), "+r"(c[1]), "+r"(c[2]), "+r"(c[3])
        : "r"(a[0]), "r"(a[1]), "r"(a[2]), "r"(a[3]), "r"(b0), "r"(b1));
}
__device__ __forceinline__ void ldsm_x4(uint32_t* r, uint32_t addr) {
    asm volatile("ldmatrix.sync.aligned.m8n8.x4.shared.b16 {%0,%1,%2,%3}, [%4];"
                 : "=r"(r[0]), "=r"(r[1]), "=r"(r[2]), "=r"(r[3]) : "r"(addr));
}
__device__ __forceinline__ void ldsm_x4_t(uint32_t* r, uint32_t addr) {
    asm volatile("ldmatrix.sync.aligned.m8n8.x4.trans.shared.b16 {%0,%1,%2,%3}, [%4];"
                 : "=r"(r[0]), "=r"(r[1]), "=r"(r[2]), "=r"(r[3]) : "r"(addr));
}

__device__ __forceinline__ uint32_t pack2(__half a, __half b) {
    __half2 t = __halves2half2(a, b);
    return *(uint32_t*)&t;
}
__device__ __forceinline__ void split2(float a, float b, uint32_t& h, uint32_t& l) {
    __half ha = __float2half_rn(a), hb = __float2half_rn(b);
    __half la = __float2half_rn(a - __half2float(ha));
    __half lb = __float2half_rn(b - __half2float(hb));
    h = pack2(ha, hb);
    l = pack2(la, lb);
}

#define SWZ(off) ((uint32_t)(off) ^ ((((uint32_t)(off)) >> 3) & 0x70u))

// ---------------------------------------------------------------------------
// Row quantizer: fp32 row[1024] -> int8 h + int8 l (x = s*(h + l/254)) + scale
// ---------------------------------------------------------------------------
__global__ __launch_bounds__(256) void rowquant(
    const float* __restrict__ in, int8_t* __restrict__ h8,
    int8_t* __restrict__ l8, float* __restrict__ scale)
{
    const size_t row = blockIdx.x;
    const int t = threadIdx.x;
    const float4 v = ((const float4*)(in + row * 1024))[t];
    float mx = fmaxf(fmaxf(fabsf(v.x), fabsf(v.y)), fmaxf(fabsf(v.z), fabsf(v.w)));
#pragma unroll
    for (int off = 16; off >= 1; off >>= 1)
        mx = fmaxf(mx, __shfl_xor_sync(0xffffffffu, mx, off));
    __shared__ float wmax[8];
    if ((t & 31) == 0) wmax[t >> 5] = mx;
    __syncthreads();
    float m = wmax[0];
#pragma unroll
    for (int i = 1; i < 8; ++i) m = fmaxf(m, wmax[i]);
    const float s   = fmaxf(m, 1e-20f) * (1.f / 127.f);
    const float inv = 1.f / s;

    float q0 = v.x * inv, q1 = v.y * inv, q2 = v.z * inv, q3 = v.w * inv;
    int h0 = __float2int_rn(q0), h1 = __float2int_rn(q1);
    int h2 = __float2int_rn(q2), h3 = __float2int_rn(q3);
    int l0 = __float2int_rn((q0 - h0) * 254.f);
    int l1 = __float2int_rn((q1 - h1) * 254.f);
    int l2 = __float2int_rn((q2 - h2) * 254.f);
    int l3 = __float2int_rn((q3 - h3) * 254.f);
    ((char4*)h8)[row * 256 + t] = make_char4((char)h0, (char)h1, (char)h2, (char)h3);
    ((char4*)l8)[row * 256 + t] = make_char4((char)l0, (char)l1, (char)l2, (char)l3);
    if (t == 0) scale[row] = s;
}

// ---------------------------------------------------------------------------
// fp32 transpose: Wt[n][k] = W[k][n]
// ---------------------------------------------------------------------------
__global__ void transpose_f32(const float* __restrict__ W,
                              float* __restrict__ Wt, int K, int N)
{
    __shared__ float t[32][33];
    int n  = blockIdx.x * 32 + threadIdx.x;
    int k0 = blockIdx.y * 32;
    for (int j = threadIdx.y; j < 32; j += 8)
        t[j][threadIdx.x] = W[(size_t)(k0 + j) * N + n];
    __syncthreads();
    int k  = blockIdx.y * 32 + threadIdx.x;
    int n0 = blockIdx.x * 32;
    for (int j = threadIdx.y; j < 32; j += 8)
        Wt[(size_t)(n0 + j) * K + k] = t[threadIdx.x][j];
}

// ---------------------------------------------------------------------------
// int8x3 GEMM: C = sA*sB*( Ah*Bh + (Ah*Bl + Al*Bh)/254 ) + bias
// CTA 128x64, 256 thr (8 warps 2m x 4n, warp 64x16), k-tile 64, double buffer.
// s32 accumulation is exact over full K (<= 3.3e7 < 2^31).
// ---------------------------------------------------------------------------
#define P8       80
#define OFF8_AH  0
#define OFF8_AL  (128 * P8)
#define OFF8_BH  (2 * 128 * P8)
#define OFF8_BL  (OFF8_BH + 64 * P8)
#define BUF8     (OFF8_BL + 64 * P8)     // 30720 B
#define GEMM8_SMEM (2 * BUF8)            // 61440 B

template<bool SPLIT>
__device__ __forceinline__ void gemm_i8_core(
    const int8_t* __restrict__ A8h, const int8_t* __restrict__ A8l,
    const float* __restrict__ sa,
    const int8_t* __restrict__ B8h, const int8_t* __restrict__ B8l,
    const float* __restrict__ sb,
    const float* __restrict__ bias, float* __restrict__ Cf,
    __half* __restrict__ Ch, __half* __restrict__ Cl,
    int N, int K, char* smem)
{
    const uint32_t sbase = smem_u32(smem);
    const int tid  = threadIdx.x;
    const int wid  = tid >> 5;
    const int lane = tid & 31;
    const int wm   = wid & 1;      // 2 m-halves of 64
    const int wn   = wid >> 1;     // 4 n-quarters of 16
    const int m0   = blockIdx.y * 128;
    const int n0   = blockIdx.x * 64;

    auto load_tile = [&](int buf, int kt) {
        uint32_t sp = sbase + buf * BUF8;
        const size_t gk = (size_t)kt * 64;
#pragma unroll
        for (int j = 0; j < 2; ++j) {
            int idx = tid + j * 256;
            int row = idx >> 2, cc = idx & 3;
            uint32_t so = (uint32_t)(row * P8 + cc * 16);
            size_t go = (size_t)(m0 + row) * K + gk + cc * 16;
            cpasync16(sp + OFF8_AH + so, A8h + go);
            cpasync16(sp + OFF8_AL + so, A8l + go);
        }
        {
            int row = tid >> 2, cc = tid & 3;
            uint32_t so = (uint32_t)(row * P8 + cc * 16);
            size_t go = (size_t)(n0 + row) * K + gk + cc * 16;
            cpasync16(sp + OFF8_BH + so, B8h + go);
            cpasync16(sp + OFF8_BL + so, B8l + go);
        }
        CP_COMMIT();
    };

    int hh[4][2][4], cx[4][2][4];
#pragma unroll
    for (int i = 0; i < 4; ++i)
#pragma unroll
        for (int j = 0; j < 2; ++j)
#pragma unroll
            for (int r = 0; r < 4; ++r) { hh[i][j][r] = 0; cx[i][j][r] = 0; }

    const uint32_t aOff = (uint32_t)((wm * 64 + (lane & 15)) * P8 + (lane >> 4) * 16);
    const uint32_t bOff = (uint32_t)((wn * 16 + (lane & 15)) * P8 + (lane >> 4) * 16);

    load_tile(0, 0);

    const int nk = K >> 6;   // k-tiles of 64
    for (int kt = 0; kt < nk; ++kt) {
        const int cur = kt & 1;
        if (kt + 1 < nk) { load_tile(cur ^ 1, kt + 1); CP_WAIT(1); }
        else             { CP_WAIT(0); }
        __syncthreads();

        const uint32_t sAH = sbase + cur * BUF8 + OFF8_AH;
        const uint32_t sAL = sbase + cur * BUF8 + OFF8_AL;
        const uint32_t sBH = sbase + cur * BUF8 + OFF8_BH;
        const uint32_t sBL = sbase + cur * BUF8 + OFF8_BL;

#pragma unroll
        for (int st = 0; st < 2; ++st) {
            const uint32_t ko = (uint32_t)(st * 32);
            uint32_t ah[4][4], al[4][4], bh[4], bl[4];
#pragma unroll
            for (int mi = 0; mi < 4; ++mi) {
                ldsm_x4(ah[mi], sAH + aOff + mi * (16 * P8) + ko);
                ldsm_x4(al[mi], sAL + aOff + mi * (16 * P8) + ko);
            }
            ldsm_x4(bh, sBH + bOff + ko);
            ldsm_x4(bl, sBL + bOff + ko);
#pragma unroll
            for (int mi = 0; mi < 4; ++mi)
#pragma unroll
                for (int ni = 0; ni < 2; ++ni) {
                    imma16832(hh[mi][ni], ah[mi], bh[ni], bh[ni + 2]);
                    imma16832(cx[mi][ni], ah[mi], bl[ni], bl[ni + 2]);
                    imma16832(cx[mi][ni], al[mi], bh[ni], bh[ni + 2]);
                }
        }
        __syncthreads();
    }

    const int lr = lane >> 2, lc = lane & 3;
    const float inv254 = 1.f / 254.f;
#pragma unroll
    for (int mi = 0; mi < 4; ++mi) {
        int r = m0 + wm * 64 + mi * 16 + lr;
        float sa0 = __ldg(sa + r), sa1 = __ldg(sa + r + 8);
#pragma unroll
        for (int ni = 0; ni < 2; ++ni) {
            int c = n0 + wn * 16 + ni * 8 + lc * 2;
            float sb0 = __ldg(sb + c), sb1 = __ldg(sb + c + 1);
            float b0 = __ldg(bias + c), b1 = __ldg(bias + c + 1);
            float v00 = sa0 * sb0 * ((float)hh[mi][ni][0] + (float)cx[mi][ni][0] * inv254) + b0;
            float v01 = sa0 * sb1 * ((float)hh[mi][ni][1] + (float)cx[mi][ni][1] * inv254) + b1;
            float v10 = sa1 * sb0 * ((float)hh[mi][ni][2] + (float)cx[mi][ni][2] * inv254) + b0;
            float v11 = sa1 * sb1 * ((float)hh[mi][ni][3] + (float)cx[mi][ni][3] * inv254) + b1;
            if (SPLIT) {
                uint32_t h, l;
                split2(v00, v01, h, l);
                *(uint32_t*)&Ch[(size_t)r * N + c] = h;
                *(uint32_t*)&Cl[(size_t)r * N + c] = l;
                split2(v10, v11, h, l);
                *(uint32_t*)&Ch[(size_t)(r + 8) * N + c] = h;
                *(uint32_t*)&Cl[(size_t)(r + 8) * N + c] = l;
            } else {
                *(float2*)&Cf[(size_t)r * N + c]       = make_float2(v00, v01);
                *(float2*)&Cf[(size_t)(r + 8) * N + c] = make_float2(v10, v11);
            }
        }
    }
}

__global__ __launch_bounds__(256, 2) void gemm_i8_split(
    const int8_t* Ah, const int8_t* Al, const float* sa,
    const int8_t* Bh, const int8_t* Bl, const float* sb,
    const float* bias, __half* Ch, __half* Cl, int N, int K)
{
    extern __shared__ char smem[];
    gemm_i8_core<true>(Ah, Al, sa, Bh, Bl, sb, bias, nullptr, Ch, Cl, N, K, smem);
}
__global__ __launch_bounds__(256, 2) void gemm_i8_f32(
    const int8_t* Ah, const int8_t* Al, const float* sa,
    const int8_t* Bh, const int8_t* Bl, const float* sb,
    const float* bias, float* Cf, int N, int K)
{
    extern __shared__ char smem[];
    gemm_i8_core<false>(Ah, Al, sa, Bh, Bl, sb, bias, Cf, nullptr, nullptr, N, K, smem);
}

// ---------------------------------------------------------------------------
// Flash attention: fp16x3, ALL f32-accum HMMA (round-8 proven structure)
// ---------------------------------------------------------------------------
#define FSM_QH   0
#define FSM_QL   16384
#define FSM_ST   32768
#define ST_KH    0
#define ST_KL    8192
#define ST_VH    16384
#define ST_VL    24576
#define ST_SZ    32768
#define FLASH_SMEM (FSM_ST + 2 * ST_SZ)   // 98304 B

__global__ __launch_bounds__(256) void flash_mma()
{
    extern __shared__ char sm[];
    const uint32_t sb = smem_u32(sm);

    const int tid  = threadIdx.x;
    const int wid  = tid >> 5;
    const int lane = tid & 31;
    const int b    = blockIdx.y >> 4;
    const int h    = blockIdx.y & 15;
    const int q0   = blockIdx.x * 128;

    {
        const size_t qtok = (size_t)(b * SQL + q0);
#pragma unroll
        for (int i = 0; i < 4; ++i) {
            int idx = i * 256 + tid;
            int r = idx >> 3, cc = idx & 7;
            uint32_t off = SWZ(r * 128 + cc * 16);
            size_t g = (qtok + r) * EMBED + h * 64 + cc * 8;
            cpasync16(sb + FSM_QH + off, g_Qh + g);
            cpasync16(sb + FSM_QL + off, g_Ql + g);
        }
    }
    auto load_kv = [&](int buf, int kb) {
        uint32_t st = sb + FSM_ST + buf * ST_SZ;
        const size_t tok = (size_t)(b * SKVL + kb * 64);
#pragma unroll
        for (int i = 0; i < 2; ++i) {
            int idx = i * 256 + tid;
            int r = idx >> 3, cc = idx & 7;
            uint32_t off = SWZ(r * 128 + cc * 16);
            size_t g = (tok + r) * EMBED + h * 64 + cc * 8;
            cpasync16(st + ST_KH + off, g_Kh + g);
            cpasync16(st + ST_KL + off, g_Kl + g);
            cpasync16(st + ST_VH + off, g_Vh + g);
            cpasync16(st + ST_VL + off, g_Vl + g);
        }
    };
    load_kv(0, 0);
    CP_COMMIT();

    float m_[2] = {-1e30f, -1e30f};
    float l_[2] = {0.f, 0.f};
    float o[8][4];
#pragma unroll
    for (int i = 0; i < 8; ++i)
#pragma unroll
        for (int j = 0; j < 4; ++j) o[i][j] = 0.f;

    const int lrow = lane & 15;
    const int lchk = lane >> 4;
    const float scale = 0.125f;

    const int NCH = SKVL / 64;
    for (int ch = 0; ch < NCH; ++ch) {
        const int cur = ch & 1;
        if (ch + 1 < NCH) { load_kv(cur ^ 1, ch + 1); CP_COMMIT(); CP_WAIT(1); }
        else              { CP_WAIT(0); }
        __syncthreads();

        const uint32_t st = sb + FSM_ST + cur * ST_SZ;

        float s[8][4];
#pragma unroll
        for (int i = 0; i < 8; ++i)
#pragma unroll
            for (int j = 0; j < 4; ++j) s[i][j] = 0.f;

#pragma unroll
        for (int kk = 0; kk < 4; ++kk) {
            uint32_t qoff = SWZ((wid * 16 + lrow) * 128 + (kk * 2 + lchk) * 16);
            uint32_t qh[4], ql[4];
            ldsm_x4(qh, sb + FSM_QH + qoff);
            ldsm_x4(ql, sb + FSM_QL + qoff);
#pragma unroll
            for (int cg = 0; cg < 4; ++cg) {
                uint32_t koff = SWZ((cg * 16 + lrow) * 128 + (kk * 2 + lchk) * 16);
                uint32_t kh[4], kl[4];
                ldsm_x4(kh, st + ST_KH + koff);
                ldsm_x4(kl, st + ST_KL + koff);
                mma16816(s[2 * cg],     qh, kh[0], kh[2]);
                mma16816(s[2 * cg],     qh, kl[0], kl[2]);
                mma16816(s[2 * cg],     ql, kh[0], kh[2]);
                mma16816(s[2 * cg + 1], qh, kh[1], kh[3]);
                mma16816(s[2 * cg + 1], qh, kl[1], kl[3]);
                mma16816(s[2 * cg + 1], ql, kh[1], kh[3]);
            }
        }

        float rm0 = -1e30f, rm1 = -1e30f;
#pragma unroll
        for (int ni = 0; ni < 8; ++ni) {
            rm0 = fmaxf(rm0, fmaxf(s[ni][0], s[ni][1]));
            rm1 = fmaxf(rm1, fmaxf(s[ni][2], s[ni][3]));
        }
        rm0 = fmaxf(rm0, __shfl_xor_sync(0xffffffffu, rm0, 1));
        rm0 = fmaxf(rm0, __shfl_xor_sync(0xffffffffu, rm0, 2));
        rm1 = fmaxf(rm1, __shfl_xor_sync(0xffffffffu, rm1, 1));
        rm1 = fmaxf(rm1, __shfl_xor_sync(0xffffffffu, rm1, 2));

        float mn0 = fmaxf(m_[0], rm0 * scale);
        float mn1 = fmaxf(m_[1], rm1 * scale);
        float a0 = __expf(m_[0] - mn0);
        float a1 = __expf(m_[1] - mn1);
        m_[0] = mn0; m_[1] = mn1;
#pragma unroll
        for (int nd = 0; nd < 8; ++nd) {
            o[nd][0] *= a0; o[nd][1] *= a0;
            o[nd][2] *= a1; o[nd][3] *= a1;
        }
        float rs0 = 0.f, rs1 = 0.f;
#pragma unroll
        for (int ni = 0; ni < 8; ++ni) {
            s[ni][0] = __expf(fmaf(s[ni][0], scale, -mn0));
            s[ni][1] = __expf(fmaf(s[ni][1], scale, -mn0));
            s[ni][2] = __expf(fmaf(s[ni][2], scale, -mn1));
            s[ni][3] = __expf(fmaf(s[ni][3], scale, -mn1));
            rs0 += s[ni][0] + s[ni][1];
            rs1 += s[ni][2] + s[ni][3];
        }
        rs0 += __shfl_xor_sync(0xffffffffu, rs0, 1);
        rs0 += __shfl_xor_sync(0xffffffffu, rs0, 2);
        rs1 += __shfl_xor_sync(0xffffffffu, rs1, 1);
        rs1 += __shfl_xor_sync(0xffffffffu, rs1, 2);
        l_[0] = l_[0] * a0 + rs0;
        l_[1] = l_[1] * a1 + rs1;

#pragma unroll
        for (int kc = 0; kc < 4; ++kc) {
            uint32_t ph[4], pl[4];
            split2(s[2 * kc][0],     s[2 * kc][1],     ph[0], pl[0]);
            split2(s[2 * kc][2],     s[2 * kc][3],     ph[1], pl[1]);
            split2(s[2 * kc + 1][0], s[2 * kc + 1][1], ph[2], pl[2]);
            split2(s[2 * kc + 1][2], s[2 * kc + 1][3], ph[3], pl[3]);
#pragma unroll
            for (int g = 0; g < 4; ++g) {
                uint32_t voff = SWZ((kc * 16 + lrow) * 128 + (g * 2 + lchk) * 16);
                uint32_t vh[4], vl[4];
                ldsm_x4_t(vh, st + ST_VH + voff);
                ldsm_x4_t(vl, st + ST_VL + voff);
                mma16816(o[2 * g],     ph, vh[0], vh[1]);
                mma16816(o[2 * g],     ph, vl[0], vl[1]);
                mma16816(o[2 * g],     pl, vh[0], vh[1]);
                mma16816(o[2 * g + 1], ph, vh[2], vh[3]);
                mma16816(o[2 * g + 1], ph, vl[2], vl[3]);
                mma16816(o[2 * g + 1], pl, vh[2], vh[3]);
            }
        }
        __syncthreads();
    }

    const float inv0 = 1.f / l_[0];
    const float inv1 = 1.f / l_[1];
    const int r0 = q0 + wid * 16 + (lane >> 2);
    const int cb = h * 64 + (lane & 3) * 2;
    const size_t tok = (size_t)b * SQL;
#pragma unroll
    for (int nd = 0; nd < 8; ++nd) {
        int c = cb + nd * 8;
        *(float2*)&g_AOf[(tok + r0) * EMBED + c] =
            make_float2(o[nd][0] * inv0, o[nd][1] * inv0);
        *(float2*)&g_AOf[(tok + r0 + 8) * EMBED + c] =
            make_float2(o[nd][2] * inv1, o[nd][3] * inv1);
    }
}

// ---------------------------------------------------------------------------
// Launch
// ---------------------------------------------------------------------------
extern "C" void kernel_launch(void* const* d_in, const int* in_sizes, int n_in,
                              void* d_out, int out_size)
{
    const float* x   = (const float*)d_in[0];
    const float* ctx = (const float*)d_in[1];
    const float* Wq  = (const float*)d_in[2];
    const float* bq  = (const float*)d_in[3];
    const float* Wk  = (const float*)d_in[4];
    const float* bk  = (const float*)d_in[5];
    const float* Wv  = (const float*)d_in[6];
    const float* bv  = (const float*)d_in[7];
    const float* Wp  = (const float*)d_in[8];
    const float* bp  = (const float*)d_in[9];
    float* out = (float*)d_out;

    int8_t *x8h, *x8l, *c8h, *c8l, *ao8h, *ao8l;
    int8_t *wq8h, *wq8l, *wk8h, *wk8l, *wv8h, *wv8l, *wp8h, *wp8l;
    float *sx, *sc, *sao, *swq, *swk, *swv, *swp, *AOf, *WtF;
    __half *Qh, *Ql, *Kh, *Kl, *Vh, *Vl;
    cudaGetSymbolAddress((void**)&x8h,  g_x8h);
    cudaGetSymbolAddress((void**)&x8l,  g_x8l);
    cudaGetSymbolAddress((void**)&c8h,  g_c8h);
    cudaGetSymbolAddress((void**)&c8l,  g_c8l);
    cudaGetSymbolAddress((void**)&ao8h, g_ao8h);
    cudaGetSymbolAddress((void**)&ao8l, g_ao8l);
    cudaGetSymbolAddress((void**)&wq8h, g_wq8h);
    cudaGetSymbolAddress((void**)&wq8l, g_wq8l);
    cudaGetSymbolAddress((void**)&wk8h, g_wk8h);
    cudaGetSymbolAddress((void**)&wk8l, g_wk8l);
    cudaGetSymbolAddress((void**)&wv8h, g_wv8h);
    cudaGetSymbolAddress((void**)&wv8l, g_wv8l);
    cudaGetSymbolAddress((void**)&wp8h, g_wp8h);
    cudaGetSymbolAddress((void**)&wp8l, g_wp8l);
    cudaGetSymbolAddress((void**)&sx,   g_sx);
    cudaGetSymbolAddress((void**)&sc,   g_sc);
    cudaGetSymbolAddress((void**)&sao,  g_sao);
    cudaGetSymbolAddress((void**)&swq,  g_swq);
    cudaGetSymbolAddress((void**)&swk,  g_swk);
    cudaGetSymbolAddress((void**)&swv,  g_swv);
    cudaGetSymbolAddress((void**)&swp,  g_swp);
    cudaGetSymbolAddress((void**)&AOf,  g_AOf);
    cudaGetSymbolAddress((void**)&WtF,  g_WtF);
    cudaGetSymbolAddress((void**)&Qh,   g_Qh);
    cudaGetSymbolAddress((void**)&Ql,   g_Ql);
    cudaGetSymbolAddress((void**)&Kh,   g_Kh);
    cudaGetSymbolAddress((void**)&Kl,   g_Kl);
    cudaGetSymbolAddress((void**)&Vh,   g_Vh);
    cudaGetSymbolAddress((void**)&Vl,   g_Vl);

    cudaFuncSetAttribute(gemm_i8_split,
                         cudaFuncAttributeMaxDynamicSharedMemorySize, GEMM8_SMEM);
    cudaFuncSetAttribute(gemm_i8_f32,
                         cudaFuncAttributeMaxDynamicSharedMemorySize, GEMM8_SMEM);
    cudaFuncSetAttribute(flash_mma,
                         cudaFuncAttributeMaxDynamicSharedMemorySize, FLASH_SMEM);

    // --- quantize activations ---
    rowquant<<<NX_ROWS, 256>>>(x,   x8h, x8l, sx);
    rowquant<<<NC_ROWS, 256>>>(ctx, c8h, c8l, sc);

    // --- transpose + quantize weights (scratch reused serially) ---
    transpose_f32<<<dim3(EMBED / 32, EMBED / 32), dim3(32, 8)>>>(Wq, WtF, EMBED, EMBED);
    rowquant<<<EMBED, 256>>>(WtF, wq8h, wq8l, swq);
    transpose_f32<<<dim3(EMBED / 32, EMBED / 32), dim3(32, 8)>>>(Wk, WtF, EMBED, EMBED);
    rowquant<<<EMBED, 256>>>(WtF, wk8h, wk8l, swk);
    transpose_f32<<<dim3(EMBED / 32, EMBED / 32), dim3(32, 8)>>>(Wv, WtF, EMBED, EMBED);
    rowquant<<<EMBED, 256>>>(WtF, wv8h, wv8l, swv);
    transpose_f32<<<dim3(VOCAB / 32, EMBED / 32), dim3(32, 8)>>>(Wp, WtF, EMBED, VOCAB);
    rowquant<<<VOCAB, 256>>>(WtF, wp8h, wp8l, swp);

    // --- projections (int8x3 IMMA) -> fp16 hi/lo Q/K/V ---
    gemm_i8_split<<<dim3(EMBED / 64, NX_ROWS / 128), 256, GEMM8_SMEM>>>(
        x8h, x8l, sx, wq8h, wq8l, swq, bq, Qh, Ql, EMBED, EMBED);
    gemm_i8_split<<<dim3(EMBED / 64, NC_ROWS / 128), 256, GEMM8_SMEM>>>(
        c8h, c8l, sc, wk8h, wk8l, swk, bk, Kh, Kl, EMBED, EMBED);
    gemm_i8_split<<<dim3(EMBED / 64, NC_ROWS / 128), 256, GEMM8_SMEM>>>(
        c8h, c8l, sc, wv8h, wv8l, swv, bv, Vh, Vl, EMBED, EMBED);

    // --- attention (fp16x3, f32-accum) -> fp32 AO ---
    flash_mma<<<dim3(SQL / 128, BATCH * NHEADS), 256, FLASH_SMEM>>>();

    // --- quantize AO, output projection ---
    rowquant<<<NX_ROWS, 256>>>(AOf, ao8h, ao8l, sao);
    gemm_i8_f32<<<dim3(VOCAB / 64, NX_ROWS / 128), 256, GEMM8_SMEM>>>(
        ao8h, ao8l, sao, wp8h, wp8l, swp, bp, out, VOCAB, EMBED);
}

// round 13
// speedup vs baseline: 2.4263x; 2.4263x over previous
#include <cuda_runtime.h>
#include <cuda_fp16.h>
#include <math.h>
#include <stdint.h>

#define EMBED  1024
#define NHEADS 16
#define HDIM   64
#define VOCAB  4096
#define BATCH  2
#define SQL    1024
#define SKVL   2048

#define NX_ROWS (BATCH * SQL)
#define NC_ROWS (BATCH * SKVL)

// ---------------------------------------------------------------------------
// Scratch (allocation-free __device__ globals)
// ---------------------------------------------------------------------------
// A-side operands: split fp16 hi/lo.  B-side operands: single fp16.
__device__ __align__(16) __half g_xh [NX_ROWS * EMBED];
__device__ __align__(16) __half g_xl [NX_ROWS * EMBED];
__device__ __align__(16) __half g_ch [NC_ROWS * EMBED];
__device__ __align__(16) __half g_cl [NC_ROWS * EMBED];
__device__ __align__(16) __half g_Qh [NX_ROWS * EMBED];   // A-side of QK^T: split
__device__ __align__(16) __half g_Ql [NX_ROWS * EMBED];
__device__ __align__(16) __half g_Kh [NC_ROWS * EMBED];   // B-side: single
__device__ __align__(16) __half g_Vh [NC_ROWS * EMBED];   // B-side: single
__device__ __align__(16) __half g_aoh[NX_ROWS * EMBED];   // A-side of out-proj: split
__device__ __align__(16) __half g_aol[NX_ROWS * EMBED];
__device__ __align__(16) __half g_WqT[EMBED * EMBED];     // B-side weights: single
__device__ __align__(16) __half g_WkT[EMBED * EMBED];
__device__ __align__(16) __half g_WvT[EMBED * EMBED];
__device__ __align__(16) __half g_WpT[VOCAB * EMBED];

// ---------------------------------------------------------------------------
// Helpers
// ---------------------------------------------------------------------------
__device__ __forceinline__ uint32_t smem_u32(const void* p) {
    uint32_t a;
    asm("{ .reg .u64 t; cvta.to.shared.u64 t, %1; cvt.u32.u64 %0, t; }"
        : "=r"(a) : "l"(p));
    return a;
}
__device__ __forceinline__ void cpasync16(uint32_t dst, const void* src) {
    asm volatile("cp.async.cg.shared.global [%0], [%1], 16;"
                 :: "r"(dst), "l"(src) : "memory");
}
#define CP_COMMIT() asm volatile("cp.async.commit_group;" ::: "memory")
#define CP_WAIT(N)  asm volatile("cp.async.wait_group %0;" :: "n"(N) : "memory")

__device__ __forceinline__ void mma16816(float* c, const uint32_t* a,
                                         uint32_t b0, uint32_t b1) {
    asm volatile(
        "mma.sync.aligned.m16n8k16.row.col.f32.f16.f16.f32 "
        "{%0,%1,%2,%3}, {%4,%5,%6,%7}, {%8,%9}, {%0,%1,%2,%3};"
        : "+f"(c[0]), "+f"(c[1]), "+f"(c[2]), "+f"(c[3])
        : "r"(a[0]), "r"(a[1]), "r"(a[2]), "r"(a[3]), "r"(b0), "r"(b1));
}
__device__ __forceinline__ void ldsm_x4(uint32_t* r, uint32_t addr) {
    asm volatile("ldmatrix.sync.aligned.m8n8.x4.shared.b16 {%0,%1,%2,%3}, [%4];"
                 : "=r"(r[0]), "=r"(r[1]), "=r"(r[2]), "=r"(r[3]) : "r"(addr));
}
__device__ __forceinline__ void ldsm_x4_t(uint32_t* r, uint32_t addr) {
    asm volatile("ldmatrix.sync.aligned.m8n8.x4.trans.shared.b16 {%0,%1,%2,%3}, [%4];"
                 : "=r"(r[0]), "=r"(r[1]), "=r"(r[2]), "=r"(r[3]) : "r"(addr));
}

__device__ __forceinline__ uint32_t pack2(__half a, __half b) {
    __half2 t = __halves2half2(a, b);
    return *(uint32_t*)&t;
}
__device__ __forceinline__ void split1(float v, __half& h, __half& l) {
    h = __float2half_rn(v);
    l = __float2half_rn(v - __half2float(h));
}
__device__ __forceinline__ void split2(float a, float b, uint32_t& h, uint32_t& l) {
    __half ha = __float2half_rn(a), hb = __float2half_rn(b);
    __half la = __float2half_rn(a - __half2float(ha));
    __half lb = __float2half_rn(b - __half2float(hb));
    h = pack2(ha, hb);
    l = pack2(la, lb);
}

#define SWZ(off) ((uint32_t)(off) ^ ((((uint32_t)(off)) >> 3) & 0x70u))

// ---------------------------------------------------------------------------
// fp32 -> fp16 hi/lo split (A-side activations)
// ---------------------------------------------------------------------------
__global__ __launch_bounds__(256) void split_f32(
    const float4* __restrict__ in,
    __half* __restrict__ hi, __half* __restrict__ lo, int n4)
{
    int i = blockIdx.x * 256 + threadIdx.x;
    if (i >= n4) return;
    float4 v = in[i];
    __half h[4], l[4];
    split1(v.x, h[0], l[0]); split1(v.y, h[1], l[1]);
    split1(v.z, h[2], l[2]); split1(v.w, h[3], l[3]);
    *(uint2*)&hi[i * 4] = *(uint2*)h;
    *(uint2*)&lo[i * 4] = *(uint2*)l;
}

// ---------------------------------------------------------------------------
// Weight transpose to single fp16 (B-side): Wt[n][k] = fp16(W[k][n])
// ---------------------------------------------------------------------------
struct TSet { const float* W; __half* Wt; };
struct TArgs { TSet s[3]; };

__device__ __forceinline__ void transpose_body(
    const float* __restrict__ W, __half* __restrict__ WT, int K, int N)
{
    __shared__ float t[32][33];
    int n  = blockIdx.x * 32 + threadIdx.x;
    int k0 = blockIdx.y * 32;
    for (int j = threadIdx.y; j < 32; j += 8)
        t[j][threadIdx.x] = W[(size_t)(k0 + j) * N + n];
    __syncthreads();
    int k  = blockIdx.y * 32 + threadIdx.x;
    int n0 = blockIdx.x * 32;
    for (int j = threadIdx.y; j < 32; j += 8)
        WT[(size_t)(n0 + j) * K + k] = __float2half_rn(t[threadIdx.x][j]);
}
__global__ void transpose_h3(TArgs a, int K, int N) {
    const TSet& s = a.s[blockIdx.z];
    transpose_body(s.W, s.Wt, K, N);
}
__global__ void transpose_h(const float* __restrict__ W,
                            __half* __restrict__ WT, int K, int N) {
    transpose_body(W, WT, K, N);
}

// ---------------------------------------------------------------------------
// fp16x2 GEMM: C = (Ah + Al) @ Bh^T + bias   (B single fp16)
// CTA 128x128, k-tile 32, 256 thr (8 warps 2m x 4n, warp 64x32),
// cp.async double buffer, ldmatrix.x4 feeding, 80B pitch.
// Output modes (runtime): fp32 C, split half (Ch+Cl), single half (Ch).
// ---------------------------------------------------------------------------
#define PITCH_B   80
#define TILE_B    (128 * PITCH_B)
#define OFF_AH    0
#define OFF_AL    (TILE_B)
#define OFF_BH    (2 * TILE_B)
#define BUF_B     (3 * TILE_B)           // 30720 B
#define GEMM_SMEM (2 * BUF_B)            // 61440 B

__device__ __forceinline__ void gemm_core(
    const __half* __restrict__ Ah, const __half* __restrict__ Al,
    const __half* __restrict__ Bh,
    const float* __restrict__ bias, float* __restrict__ Cf,
    __half* __restrict__ Ch, __half* __restrict__ Cl,
    int N, int K, char* smem)
{
    const uint32_t sbase = smem_u32(smem);

    const int tid  = threadIdx.x;
    const int wid  = tid >> 5;
    const int lane = tid & 31;
    const int wm   = wid & 1;
    const int wn   = wid >> 1;
    const int lr   = lane >> 2;
    const int lc   = lane & 3;

    const int m0 = blockIdx.y * 128;
    const int n0 = blockIdx.x * 128;

    const int lrow0 = tid >> 2;
    const int lcc0  = tid & 3;

    const size_t aBase = (size_t)m0 * K;
    const size_t bBase = (size_t)n0 * K;

    auto load_tile = [&](int buf, int kt) {
        uint32_t sp = sbase + buf * BUF_B;
        const size_t gk = (size_t)kt * 32;
#pragma unroll
        for (int j = 0; j < 2; ++j) {
            int row = lrow0 + j * 64;
            uint32_t so = (uint32_t)(row * PITCH_B + lcc0 * 16);
            size_t   ga = aBase + (size_t)row * K + gk + lcc0 * 8;
            cpasync16(sp + OFF_AH + so, Ah + ga);
            cpasync16(sp + OFF_AL + so, Al + ga);
            size_t   gb = bBase + (size_t)row * K + gk + lcc0 * 8;
            cpasync16(sp + OFF_BH + so, Bh + gb);
        }
        CP_COMMIT();
    };

    float acc[4][4][4];
#pragma unroll
    for (int i = 0; i < 4; ++i)
#pragma unroll
        for (int j = 0; j < 4; ++j)
#pragma unroll
            for (int r = 0; r < 4; ++r) acc[i][j][r] = 0.f;

    const uint32_t aOff = (uint32_t)((wm * 64 + (lane & 15)) * PITCH_B
                                     + (lane >> 4) * 16);
    const uint32_t bOff = (uint32_t)((wn * 32 + (lane & 15)) * PITCH_B
                                     + (lane >> 4) * 16);

    load_tile(0, 0);

    const int nk = K >> 5;
    for (int kt = 0; kt < nk; ++kt) {
        const int cur = kt & 1;
        if (kt + 1 < nk) { load_tile(cur ^ 1, kt + 1); CP_WAIT(1); }
        else             { CP_WAIT(0); }
        __syncthreads();

        const uint32_t sAH = sbase + cur * BUF_B + OFF_AH;
        const uint32_t sAL = sbase + cur * BUF_B + OFF_AL;
        const uint32_t sBH = sbase + cur * BUF_B + OFF_BH;

#pragma unroll
        for (int ks = 0; ks < 2; ++ks) {
            const uint32_t ko = (uint32_t)(ks * 32);

            uint32_t ah[4][4];
#pragma unroll
            for (int mi = 0; mi < 4; ++mi)
                ldsm_x4(ah[mi], sAH + aOff + mi * (16 * PITCH_B) + ko);
            uint32_t bh[2][4];
#pragma unroll
            for (int g = 0; g < 2; ++g)
                ldsm_x4(bh[g], sBH + bOff + g * (16 * PITCH_B) + ko);

#pragma unroll
            for (int mi = 0; mi < 4; ++mi)
#pragma unroll
                for (int ni = 0; ni < 4; ++ni)
                    mma16816(acc[mi][ni], ah[mi],
                             bh[ni >> 1][ni & 1], bh[ni >> 1][(ni & 1) + 2]);

#pragma unroll
            for (int mi = 0; mi < 4; ++mi) {
                uint32_t al[4];
                ldsm_x4(al, sAL + aOff + mi * (16 * PITCH_B) + ko);
#pragma unroll
                for (int ni = 0; ni < 4; ++ni)
                    mma16816(acc[mi][ni], al,
                             bh[ni >> 1][ni & 1], bh[ni >> 1][(ni & 1) + 2]);
            }
        }
        __syncthreads();
    }

#pragma unroll
    for (int mi = 0; mi < 4; ++mi) {
        int r = m0 + wm * 64 + mi * 16 + lr;
#pragma unroll
        for (int ni = 0; ni < 4; ++ni) {
            int c = n0 + wn * 32 + ni * 8 + lc * 2;
            float b0 = __ldg(bias + c), b1 = __ldg(bias + c + 1);
            float v00 = acc[mi][ni][0] + b0, v01 = acc[mi][ni][1] + b1;
            float v10 = acc[mi][ni][2] + b0, v11 = acc[mi][ni][3] + b1;
            if (Cf) {
                *(float2*)&Cf[(size_t)r * N + c]       = make_float2(v00, v01);
                *(float2*)&Cf[(size_t)(r + 8) * N + c] = make_float2(v10, v11);
            } else if (Cl) {
                uint32_t h, l;
                split2(v00, v01, h, l);
                *(uint32_t*)&Ch[(size_t)r * N + c] = h;
                *(uint32_t*)&Cl[(size_t)r * N + c] = l;
                split2(v10, v11, h, l);
                *(uint32_t*)&Ch[(size_t)(r + 8) * N + c] = h;
                *(uint32_t*)&Cl[(size_t)(r + 8) * N + c] = l;
            } else {
                *(uint32_t*)&Ch[(size_t)r * N + c] =
                    pack2(__float2half_rn(v00), __float2half_rn(v01));
                *(uint32_t*)&Ch[(size_t)(r + 8) * N + c] =
                    pack2(__float2half_rn(v10), __float2half_rn(v11));
            }
        }
    }
}

__global__ __launch_bounds__(256, 2) void gemm_out(
    const __half* Ah, const __half* Al, const __half* Bh,
    const float* bias, float* C, int N, int K)
{
    extern __shared__ char smem[];
    gemm_core(Ah, Al, Bh, bias, C, nullptr, nullptr, N, K, smem);
}

struct GSet {
    const __half *Ah, *Al, *Bh;
    const float* bias;
    __half *Ch, *Cl;    // Cl == nullptr -> single-half output
};
struct QKVArgs { GSet s[3]; };

__global__ __launch_bounds__(256, 2) void gemm_qkv(QKVArgs a)
{
    extern __shared__ char smem[];
    if (blockIdx.z == 0 && blockIdx.y >= NX_ROWS / 128) return;
    const GSet& s = a.s[blockIdx.z];
    gemm_core(s.Ah, s.Al, s.Bh, s.bias, nullptr, s.Ch, s.Cl, EMBED, EMBED, smem);
}

// ---------------------------------------------------------------------------
// Flash attention (fp16x2: Q split / K single; P split / V single)
// ---------------------------------------------------------------------------
#define FSM_QH   0
#define FSM_QL   16384
#define FSM_ST   32768
#define ST_KH    0
#define ST_VH    8192
#define ST_SZ    16384
#define FLASH_SMEM (FSM_ST + 2 * ST_SZ)   // 65536 B

__global__ __launch_bounds__(256) void flash_mma()
{
    extern __shared__ char sm[];
    const uint32_t sb = smem_u32(sm);

    const int tid  = threadIdx.x;
    const int wid  = tid >> 5;
    const int lane = tid & 31;
    const int b    = blockIdx.y >> 4;
    const int h    = blockIdx.y & 15;
    const int q0   = blockIdx.x * 128;

    {
        const size_t qtok = (size_t)(b * SQL + q0);
#pragma unroll
        for (int i = 0; i < 4; ++i) {
            int idx = i * 256 + tid;
            int r = idx >> 3, cc = idx & 7;
            uint32_t off = SWZ(r * 128 + cc * 16);
            size_t g = (qtok + r) * EMBED + h * 64 + cc * 8;
            cpasync16(sb + FSM_QH + off, g_Qh + g);
            cpasync16(sb + FSM_QL + off, g_Ql + g);
        }
    }
    auto load_kv = [&](int buf, int kb) {
        uint32_t st = sb + FSM_ST + buf * ST_SZ;
        const size_t tok = (size_t)(b * SKVL + kb * 64);
#pragma unroll
        for (int i = 0; i < 2; ++i) {
            int idx = i * 256 + tid;
            int r = idx >> 3, cc = idx & 7;
            uint32_t off = SWZ(r * 128 + cc * 16);
            size_t g = (tok + r) * EMBED + h * 64 + cc * 8;
            cpasync16(st + ST_KH + off, g_Kh + g);
            cpasync16(st + ST_VH + off, g_Vh + g);
        }
    };
    load_kv(0, 0);
    CP_COMMIT();

    float m_[2] = {-1e30f, -1e30f};
    float l_[2] = {0.f, 0.f};
    float o[8][4];
#pragma unroll
    for (int i = 0; i < 8; ++i)
#pragma unroll
        for (int j = 0; j < 4; ++j) o[i][j] = 0.f;

    const int lrow = lane & 15;
    const int lchk = lane >> 4;
    const float scale = 0.125f;

    const int NCH = SKVL / 64;
    for (int ch = 0; ch < NCH; ++ch) {
        const int cur = ch & 1;
        if (ch + 1 < NCH) { load_kv(cur ^ 1, ch + 1); CP_COMMIT(); CP_WAIT(1); }
        else              { CP_WAIT(0); }
        __syncthreads();

        const uint32_t st = sb + FSM_ST + cur * ST_SZ;

        float s[8][4];
#pragma unroll
        for (int i = 0; i < 8; ++i)
#pragma unroll
            for (int j = 0; j < 4; ++j) s[i][j] = 0.f;

#pragma unroll
        for (int kk = 0; kk < 4; ++kk) {
            uint32_t qoff = SWZ((wid * 16 + lrow) * 128 + (kk * 2 + lchk) * 16);
            uint32_t qh[4], ql[4];
            ldsm_x4(qh, sb + FSM_QH + qoff);
            ldsm_x4(ql, sb + FSM_QL + qoff);
#pragma unroll
            for (int cg = 0; cg < 4; ++cg) {
                uint32_t koff = SWZ((cg * 16 + lrow) * 128 + (kk * 2 + lchk) * 16);
                uint32_t kh[4];
                ldsm_x4(kh, st + ST_KH + koff);
                mma16816(s[2 * cg],     qh, kh[0], kh[2]);
                mma16816(s[2 * cg],     ql, kh[0], kh[2]);
                mma16816(s[2 * cg + 1], qh, kh[1], kh[3]);
                mma16816(s[2 * cg + 1], ql, kh[1], kh[3]);
            }
        }

        float rm0 = -1e30f, rm1 = -1e30f;
#pragma unroll
        for (int ni = 0; ni < 8; ++ni) {
            rm0 = fmaxf(rm0, fmaxf(s[ni][0], s[ni][1]));
            rm1 = fmaxf(rm1, fmaxf(s[ni][2], s[ni][3]));
        }
        rm0 = fmaxf(rm0, __shfl_xor_sync(0xffffffffu, rm0, 1));
        rm0 = fmaxf(rm0, __shfl_xor_sync(0xffffffffu, rm0, 2));
        rm1 = fmaxf(rm1, __shfl_xor_sync(0xffffffffu, rm1, 1));
        rm1 = fmaxf(rm1, __shfl_xor_sync(0xffffffffu, rm1, 2));

        float mn0 = fmaxf(m_[0], rm0 * scale);
        float mn1 = fmaxf(m_[1], rm1 * scale);
        float a0 = __expf(m_[0] - mn0);
        float a1 = __expf(m_[1] - mn1);
        m_[0] = mn0; m_[1] = mn1;
#pragma unroll
        for (int nd = 0; nd < 8; ++nd) {
            o[nd][0] *= a0; o[nd][1] *= a0;
            o[nd][2] *= a1; o[nd][3] *= a1;
        }
        float rs0 = 0.f, rs1 = 0.f;
#pragma unroll
        for (int ni = 0; ni < 8; ++ni) {
            s[ni][0] = __expf(fmaf(s[ni][0], scale, -mn0));
            s[ni][1] = __expf(fmaf(s[ni][1], scale, -mn0));
            s[ni][2] = __expf(fmaf(s[ni][2], scale, -mn1));
            s[ni][3] = __expf(fmaf(s[ni][3], scale, -mn1));
            rs0 += s[ni][0] + s[ni][1];
            rs1 += s[ni][2] + s[ni][3];
        }
        rs0 += __shfl_xor_sync(0xffffffffu, rs0, 1);
        rs0 += __shfl_xor_sync(0xffffffffu, rs0, 2);
        rs1 += __shfl_xor_sync(0xffffffffu, rs1, 1);
        rs1 += __shfl_xor_sync(0xffffffffu, rs1, 2);
        l_[0] = l_[0] * a0 + rs0;
        l_[1] = l_[1] * a1 + rs1;

#pragma unroll
        for (int kc = 0; kc < 4; ++kc) {
            uint32_t ph[4], pl[4];
            split2(s[2 * kc][0],     s[2 * kc][1],     ph[0], pl[0]);
            split2(s[2 * kc][2],     s[2 * kc][3],     ph[1], pl[1]);
            split2(s[2 * kc + 1][0], s[2 * kc + 1][1], ph[2], pl[2]);
            split2(s[2 * kc + 1][2], s[2 * kc + 1][3], ph[3], pl[3]);
#pragma unroll
            for (int g = 0; g < 4; ++g) {
                uint32_t voff = SWZ((kc * 16 + lrow) * 128 + (g * 2 + lchk) * 16);
                uint32_t vh[4];
                ldsm_x4_t(vh, st + ST_VH + voff);
                mma16816(o[2 * g],     ph, vh[0], vh[1]);
                mma16816(o[2 * g],     pl, vh[0], vh[1]);
                mma16816(o[2 * g + 1], ph, vh[2], vh[3]);
                mma16816(o[2 * g + 1], pl, vh[2], vh[3]);
            }
        }
        __syncthreads();
    }

    const float inv0 = 1.f / l_[0];
    const float inv1 = 1.f / l_[1];
    const int r0 = q0 + wid * 16 + (lane >> 2);
    const int cb = h * 64 + (lane & 3) * 2;
    const size_t tok = (size_t)b * SQL;
#pragma unroll
    for (int nd = 0; nd < 8; ++nd) {
        int c = cb + nd * 8;
        uint32_t hh, ll;
        split2(o[nd][0] * inv0, o[nd][1] * inv0, hh, ll);
        *(uint32_t*)&g_aoh[(tok + r0) * EMBED + c] = hh;
        *(uint32_t*)&g_aol[(tok + r0) * EMBED + c] = ll;
        split2(o[nd][2] * inv1, o[nd][3] * inv1, hh, ll);
        *(uint32_t*)&g_aoh[(tok + r0 + 8) * EMBED + c] = hh;
        *(uint32_t*)&g_aol[(tok + r0 + 8) * EMBED + c] = ll;
    }
}

// ---------------------------------------------------------------------------
// Launch
// ---------------------------------------------------------------------------
extern "C" void kernel_launch(void* const* d_in, const int* in_sizes, int n_in,
                              void* d_out, int out_size)
{
    const float* x   = (const float*)d_in[0];
    const float* ctx = (const float*)d_in[1];
    const float* Wq  = (const float*)d_in[2];
    const float* bq  = (const float*)d_in[3];
    const float* Wk  = (const float*)d_in[4];
    const float* bk  = (const float*)d_in[5];
    const float* Wv  = (const float*)d_in[6];
    const float* bv  = (const float*)d_in[7];
    const float* Wp  = (const float*)d_in[8];
    const float* bp  = (const float*)d_in[9];
    float* out = (float*)d_out;

    __half *xh, *xl, *ch_, *cl_, *Qh, *Ql, *Kh, *Vh, *aoh, *aol;
    __half *WqT, *WkT, *WvT, *WpT;
    cudaGetSymbolAddress((void**)&xh,  g_xh);
    cudaGetSymbolAddress((void**)&xl,  g_xl);
    cudaGetSymbolAddress((void**)&ch_, g_ch);
    cudaGetSymbolAddress((void**)&cl_, g_cl);
    cudaGetSymbolAddress((void**)&Qh,  g_Qh);
    cudaGetSymbolAddress((void**)&Ql,  g_Ql);
    cudaGetSymbolAddress((void**)&Kh,  g_Kh);
    cudaGetSymbolAddress((void**)&Vh,  g_Vh);
    cudaGetSymbolAddress((void**)&aoh, g_aoh);
    cudaGetSymbolAddress((void**)&aol, g_aol);
    cudaGetSymbolAddress((void**)&WqT, g_WqT);
    cudaGetSymbolAddress((void**)&WkT, g_WkT);
    cudaGetSymbolAddress((void**)&WvT, g_WvT);
    cudaGetSymbolAddress((void**)&WpT, g_WpT);

    cudaFuncSetAttribute(gemm_qkv,
                         cudaFuncAttributeMaxDynamicSharedMemorySize, GEMM_SMEM);
    cudaFuncSetAttribute(gemm_out,
                         cudaFuncAttributeMaxDynamicSharedMemorySize, GEMM_SMEM);
    cudaFuncSetAttribute(flash_mma,
                         cudaFuncAttributeMaxDynamicSharedMemorySize, FLASH_SMEM);

    const int NX = NX_ROWS * EMBED;
    const int NC = NC_ROWS * EMBED;

    // Split activations (A-side)
    split_f32<<<(NX / 4 + 255) / 256, 256>>>((const float4*)x,   xh,  xl,  NX / 4);
    split_f32<<<(NC / 4 + 255) / 256, 256>>>((const float4*)ctx, ch_, cl_, NC / 4);

    // Transpose weights to single fp16 (B-side)
    TArgs ta;
    ta.s[0] = {Wq, WqT};
    ta.s[1] = {Wk, WkT};
    ta.s[2] = {Wv, WvT};
    transpose_h3<<<dim3(EMBED / 32, EMBED / 32, 3), dim3(32, 8)>>>(ta, EMBED, EMBED);
    transpose_h<<<dim3(VOCAB / 32, EMBED / 32), dim3(32, 8)>>>(Wp, WpT, EMBED, VOCAB);

    // Fused Q/K/V projections (Q -> split, K/V -> single)
    QKVArgs qa;
    qa.s[0] = {xh,  xl,  WqT, bq, Qh, Ql};
    qa.s[1] = {ch_, cl_, WkT, bk, Kh, nullptr};
    qa.s[2] = {ch_, cl_, WvT, bv, Vh, nullptr};
    gemm_qkv<<<dim3(EMBED / 128, NC_ROWS / 128, 3), 256, GEMM_SMEM>>>(qa);

    // Flash attention -> split AO
    flash_mma<<<dim3(SQL / 128, BATCH * NHEADS), 256, FLASH_SMEM>>>();

    // Output projection
    gemm_out<<<dim3(VOCAB / 128, NX_ROWS / 128), 256, GEMM_SMEM>>>(
        aoh, aol, WpT, bp, out, VOCAB, EMBED);
}

// round 15
// speedup vs baseline: 3.6513x; 1.5049x over previous
#include <cuda_runtime.h>
#include <cuda_fp16.h>
#include <math.h>
#include <stdint.h>

#define EMBED  1024
#define NHEADS 16
#define HDIM   64
#define VOCAB  4096
#define BATCH  2
#define SQL    1024
#define SKVL   2048

#define NX_ROWS (BATCH * SQL)
#define NC_ROWS (BATCH * SKVL)

// ---------------------------------------------------------------------------
// Scratch (allocation-free __device__ globals) — all single fp16 except P
// (which lives only in registers, split) .
// ---------------------------------------------------------------------------
__device__ __align__(16) __half g_xh [NX_ROWS * EMBED];
__device__ __align__(16) __half g_ch [NC_ROWS * EMBED];
__device__ __align__(16) __half g_Qh [NX_ROWS * EMBED];
__device__ __align__(16) __half g_Kh [NC_ROWS * EMBED];
__device__ __align__(16) __half g_Vh [NC_ROWS * EMBED];
__device__ __align__(16) __half g_aoh[NX_ROWS * EMBED];
__device__ __align__(16) __half g_WqT[EMBED * EMBED];
__device__ __align__(16) __half g_WkT[EMBED * EMBED];
__device__ __align__(16) __half g_WvT[EMBED * EMBED];
__device__ __align__(16) __half g_WpT[VOCAB * EMBED];

// ---------------------------------------------------------------------------
// Helpers
// ---------------------------------------------------------------------------
__device__ __forceinline__ uint32_t smem_u32(const void* p) {
    uint32_t a;
    asm("{ .reg .u64 t; cvta.to.shared.u64 t, %1; cvt.u32.u64 %0, t; }"
        : "=r"(a) : "l"(p));
    return a;
}
__device__ __forceinline__ void cpasync16(uint32_t dst, const void* src) {
    asm volatile("cp.async.cg.shared.global [%0], [%1], 16;"
                 :: "r"(dst), "l"(src) : "memory");
}
#define CP_COMMIT() asm volatile("cp.async.commit_group;" ::: "memory")
#define CP_WAIT(N)  asm volatile("cp.async.wait_group %0;" :: "n"(N) : "memory")

__device__ __forceinline__ void mma16816(float* c, const uint32_t* a,
                                         uint32_t b0, uint32_t b1) {
    asm volatile(
        "mma.sync.aligned.m16n8k16.row.col.f32.f16.f16.f32 "
        "{%0,%1,%2,%3}, {%4,%5,%6,%7}, {%8,%9}, {%0,%1,%2,%3};"
        : "+f"(c[0]), "+f"(c[1]), "+f"(c[2]), "+f"(c[3])
        : "r"(a[0]), "r"(a[1]), "r"(a[2]), "r"(a[3]), "r"(b0), "r"(b1));
}
__device__ __forceinline__ void ldsm_x4(uint32_t* r, uint32_t addr) {
    asm volatile("ldmatrix.sync.aligned.m8n8.x4.shared.b16 {%0,%1,%2,%3}, [%4];"
                 : "=r"(r[0]), "=r"(r[1]), "=r"(r[2]), "=r"(r[3]) : "r"(addr));
}
__device__ __forceinline__ void ldsm_x4_t(uint32_t* r, uint32_t addr) {
    asm volatile("ldmatrix.sync.aligned.m8n8.x4.trans.shared.b16 {%0,%1,%2,%3}, [%4];"
                 : "=r"(r[0]), "=r"(r[1]), "=r"(r[2]), "=r"(r[3]) : "r"(addr));
}

__device__ __forceinline__ uint32_t pack2(__half a, __half b) {
    __half2 t = __halves2half2(a, b);
    return *(uint32_t*)&t;
}
__device__ __forceinline__ void split2(float a, float b, uint32_t& h, uint32_t& l) {
    __half ha = __float2half_rn(a), hb = __float2half_rn(b);
    __half la = __float2half_rn(a - __half2float(ha));
    __half lb = __float2half_rn(b - __half2float(hb));
    h = pack2(ha, hb);
    l = pack2(la, lb);
}

#define SWZ(off) ((uint32_t)(off) ^ ((((uint32_t)(off)) >> 3) & 0x70u))

// ---------------------------------------------------------------------------
// fp32 -> fp16 convert (single)
// ---------------------------------------------------------------------------
__global__ __launch_bounds__(256) void cvt_f32h(
    const float4* __restrict__ in, __half* __restrict__ out, int n4)
{
    int i = blockIdx.x * 256 + threadIdx.x;
    if (i >= n4) return;
    float4 v = in[i];
    __half h[4] = {__float2half_rn(v.x), __float2half_rn(v.y),
                   __float2half_rn(v.z), __float2half_rn(v.w)};
    *(uint2*)&out[i * 4] = *(uint2*)h;
}

// ---------------------------------------------------------------------------
// Weight transpose to fp16: Wt[n][k] = fp16(W[k][n])
// ---------------------------------------------------------------------------
struct TSet { const float* W; __half* Wt; };
struct TArgs { TSet s[3]; };

__device__ __forceinline__ void transpose_body(
    const float* __restrict__ W, __half* __restrict__ WT, int K, int N)
{
    __shared__ float t[32][33];
    int n  = blockIdx.x * 32 + threadIdx.x;
    int k0 = blockIdx.y * 32;
    for (int j = threadIdx.y; j < 32; j += 8)
        t[j][threadIdx.x] = W[(size_t)(k0 + j) * N + n];
    __syncthreads();
    int k  = blockIdx.y * 32 + threadIdx.x;
    int n0 = blockIdx.x * 32;
    for (int j = threadIdx.y; j < 32; j += 8)
        WT[(size_t)(n0 + j) * K + k] = __float2half_rn(t[threadIdx.x][j]);
}
__global__ void transpose_h3(TArgs a, int K, int N) {
    const TSet& s = a.s[blockIdx.z];
    transpose_body(s.W, s.Wt, K, N);
}
__global__ void transpose_h(const float* __restrict__ W,
                            __half* __restrict__ WT, int K, int N) {
    transpose_body(W, WT, K, N);
}

// ---------------------------------------------------------------------------
// fp16 GEMM (1-term): C = A @ B^T + bias
// CTA 128x128, k-tile 32, 256 thr (8 warps 2m x 4n, warp 64x32),
// cp.async double buffer, ldmatrix.x4 feeding, 80B pitch.
// ---------------------------------------------------------------------------
#define PITCH_B   80
#define TILE_B    (128 * PITCH_B)
#define OFF_AH    0
#define OFF_BH    (TILE_B)
#define BUF_B     (2 * TILE_B)           // 20480 B
#define GEMM_SMEM (2 * BUF_B)            // 40960 B

__device__ __forceinline__ void gemm_core(
    const __half* __restrict__ Ah, const __half* __restrict__ Bh,
    const float* __restrict__ bias, float* __restrict__ Cf,
    __half* __restrict__ Ch, int N, int K, char* smem)
{
    const uint32_t sbase = smem_u32(smem);

    const int tid  = threadIdx.x;
    const int wid  = tid >> 5;
    const int lane = tid & 31;
    const int wm   = wid & 1;
    const int wn   = wid >> 1;
    const int lr   = lane >> 2;
    const int lc   = lane & 3;

    const int m0 = blockIdx.y * 128;
    const int n0 = blockIdx.x * 128;

    const int lrow0 = tid >> 2;
    const int lcc0  = tid & 3;

    const size_t aBase = (size_t)m0 * K;
    const size_t bBase = (size_t)n0 * K;

    auto load_tile = [&](int buf, int kt) {
        uint32_t sp = sbase + buf * BUF_B;
        const size_t gk = (size_t)kt * 32;
#pragma unroll
        for (int j = 0; j < 2; ++j) {
            int row = lrow0 + j * 64;
            uint32_t so = (uint32_t)(row * PITCH_B + lcc0 * 16);
            cpasync16(sp + OFF_AH + so, Ah + aBase + (size_t)row * K + gk + lcc0 * 8);
            cpasync16(sp + OFF_BH + so, Bh + bBase + (size_t)row * K + gk + lcc0 * 8);
        }
        CP_COMMIT();
    };

    float acc[4][4][4];
#pragma unroll
    for (int i = 0; i < 4; ++i)
#pragma unroll
        for (int j = 0; j < 4; ++j)
#pragma unroll
            for (int r = 0; r < 4; ++r) acc[i][j][r] = 0.f;

    const uint32_t aOff = (uint32_t)((wm * 64 + (lane & 15)) * PITCH_B
                                     + (lane >> 4) * 16);
    const uint32_t bOff = (uint32_t)((wn * 32 + (lane & 15)) * PITCH_B
                                     + (lane >> 4) * 16);

    load_tile(0, 0);

    const int nk = K >> 5;
    for (int kt = 0; kt < nk; ++kt) {
        const int cur = kt & 1;
        if (kt + 1 < nk) { load_tile(cur ^ 1, kt + 1); CP_WAIT(1); }
        else             { CP_WAIT(0); }
        __syncthreads();

        const uint32_t sAH = sbase + cur * BUF_B + OFF_AH;
        const uint32_t sBH = sbase + cur * BUF_B + OFF_BH;

#pragma unroll
        for (int ks = 0; ks < 2; ++ks) {
            const uint32_t ko = (uint32_t)(ks * 32);

            uint32_t ah[4][4];
#pragma unroll
            for (int mi = 0; mi < 4; ++mi)
                ldsm_x4(ah[mi], sAH + aOff + mi * (16 * PITCH_B) + ko);
            uint32_t bh[2][4];
#pragma unroll
            for (int g = 0; g < 2; ++g)
                ldsm_x4(bh[g], sBH + bOff + g * (16 * PITCH_B) + ko);

#pragma unroll
            for (int mi = 0; mi < 4; ++mi)
#pragma unroll
                for (int ni = 0; ni < 4; ++ni)
                    mma16816(acc[mi][ni], ah[mi],
                             bh[ni >> 1][ni & 1], bh[ni >> 1][(ni & 1) + 2]);
        }
        __syncthreads();
    }

#pragma unroll
    for (int mi = 0; mi < 4; ++mi) {
        int r = m0 + wm * 64 + mi * 16 + lr;
#pragma unroll
        for (int ni = 0; ni < 4; ++ni) {
            int c = n0 + wn * 32 + ni * 8 + lc * 2;
            float b0 = __ldg(bias + c), b1 = __ldg(bias + c + 1);
            float v00 = acc[mi][ni][0] + b0, v01 = acc[mi][ni][1] + b1;
            float v10 = acc[mi][ni][2] + b0, v11 = acc[mi][ni][3] + b1;
            if (Cf) {
                *(float2*)&Cf[(size_t)r * N + c]       = make_float2(v00, v01);
                *(float2*)&Cf[(size_t)(r + 8) * N + c] = make_float2(v10, v11);
            } else {
                *(uint32_t*)&Ch[(size_t)r * N + c] =
                    pack2(__float2half_rn(v00), __float2half_rn(v01));
                *(uint32_t*)&Ch[(size_t)(r + 8) * N + c] =
                    pack2(__float2half_rn(v10), __float2half_rn(v11));
            }
        }
    }
}

__global__ __launch_bounds__(256, 2) void gemm_out(
    const __half* Ah, const __half* Bh,
    const float* bias, float* C, int N, int K)
{
    extern __shared__ char smem[];
    gemm_core(Ah, Bh, bias, C, nullptr, N, K, smem);
}

struct GSet {
    const __half *Ah, *Bh;
    const float* bias;
    __half *Ch;
};
struct QKVArgs { GSet s[3]; };

__global__ __launch_bounds__(256, 2) void gemm_qkv(QKVArgs a)
{
    extern __shared__ char smem[];
    if (blockIdx.z == 0 && blockIdx.y >= NX_ROWS / 128) return;
    const GSet& s = a.s[blockIdx.z];
    gemm_core(s.Ah, s.Bh, s.bias, nullptr, s.Ch, EMBED, EMBED, smem);
}

// ---------------------------------------------------------------------------
// Flash attention: QK^T 1-term (Q,K single fp16); PV 2-term (P split, V single)
// ---------------------------------------------------------------------------
#define FSM_QH   0
#define FSM_ST   16384
#define ST_KH    0
#define ST_VH    8192
#define ST_SZ    16384
#define FLASH_SMEM (FSM_ST + 2 * ST_SZ)   // 49152 B

__global__ __launch_bounds__(256) void flash_mma()
{
    extern __shared__ char sm[];
    const uint32_t sb = smem_u32(sm);

    const int tid  = threadIdx.x;
    const int wid  = tid >> 5;
    const int lane = tid & 31;
    const int b    = blockIdx.y >> 4;
    const int h    = blockIdx.y & 15;
    const int q0   = blockIdx.x * 128;

    {
        const size_t qtok = (size_t)(b * SQL + q0);
#pragma unroll
        for (int i = 0; i < 4; ++i) {
            int idx = i * 256 + tid;
            int r = idx >> 3, cc = idx & 7;
            uint32_t off = SWZ(r * 128 + cc * 16);
            cpasync16(sb + FSM_QH + off, g_Qh + (qtok + r) * EMBED + h * 64 + cc * 8);
        }
    }
    auto load_kv = [&](int buf, int kb) {
        uint32_t st = sb + FSM_ST + buf * ST_SZ;
        const size_t tok = (size_t)(b * SKVL + kb * 64);
#pragma unroll
        for (int i = 0; i < 2; ++i) {
            int idx = i * 256 + tid;
            int r = idx >> 3, cc = idx & 7;
            uint32_t off = SWZ(r * 128 + cc * 16);
            size_t g = (tok + r) * EMBED + h * 64 + cc * 8;
            cpasync16(st + ST_KH + off, g_Kh + g);
            cpasync16(st + ST_VH + off, g_Vh + g);
        }
    };
    load_kv(0, 0);
    CP_COMMIT();

    float m_[2] = {-1e30f, -1e30f};
    float l_[2] = {0.f, 0.f};
    float o[8][4];
#pragma unroll
    for (int i = 0; i < 8; ++i)
#pragma unroll
        for (int j = 0; j < 4; ++j) o[i][j] = 0.f;

    const int lrow = lane & 15;
    const int lchk = lane >> 4;
    const float scale = 0.125f;

    const int NCH = SKVL / 64;
    for (int ch = 0; ch < NCH; ++ch) {
        const int cur = ch & 1;
        if (ch + 1 < NCH) { load_kv(cur ^ 1, ch + 1); CP_COMMIT(); CP_WAIT(1); }
        else              { CP_WAIT(0); }
        __syncthreads();

        const uint32_t st = sb + FSM_ST + cur * ST_SZ;

        float s[8][4];
#pragma unroll
        for (int i = 0; i < 8; ++i)
#pragma unroll
            for (int j = 0; j < 4; ++j) s[i][j] = 0.f;

#pragma unroll
        for (int kk = 0; kk < 4; ++kk) {
            uint32_t qoff = SWZ((wid * 16 + lrow) * 128 + (kk * 2 + lchk) * 16);
            uint32_t qh[4];
            ldsm_x4(qh, sb + FSM_QH + qoff);
#pragma unroll
            for (int cg = 0; cg < 4; ++cg) {
                uint32_t koff = SWZ((cg * 16 + lrow) * 128 + (kk * 2 + lchk) * 16);
                uint32_t kh[4];
                ldsm_x4(kh, st + ST_KH + koff);
                mma16816(s[2 * cg],     qh, kh[0], kh[2]);
                mma16816(s[2 * cg + 1], qh, kh[1], kh[3]);
            }
        }

        float rm0 = -1e30f, rm1 = -1e30f;
#pragma unroll
        for (int ni = 0; ni < 8; ++ni) {
            rm0 = fmaxf(rm0, fmaxf(s[ni][0], s[ni][1]));
            rm1 = fmaxf(rm1, fmaxf(s[ni][2], s[ni][3]));
        }
        rm0 = fmaxf(rm0, __shfl_xor_sync(0xffffffffu, rm0, 1));
        rm0 = fmaxf(rm0, __shfl_xor_sync(0xffffffffu, rm0, 2));
        rm1 = fmaxf(rm1, __shfl_xor_sync(0xffffffffu, rm1, 1));
        rm1 = fmaxf(rm1, __shfl_xor_sync(0xffffffffu, rm1, 2));

        float mn0 = fmaxf(m_[0], rm0 * scale);
        float mn1 = fmaxf(m_[1], rm1 * scale);
        float a0 = __expf(m_[0] - mn0);
        float a1 = __expf(m_[1] - mn1);
        m_[0] = mn0; m_[1] = mn1;
#pragma unroll
        for (int nd = 0; nd < 8; ++nd) {
            o[nd][0] *= a0; o[nd][1] *= a0;
            o[nd][2] *= a1; o[nd][3] *= a1;
        }
        float rs0 = 0.f, rs1 = 0.f;
#pragma unroll
        for (int ni = 0; ni < 8; ++ni) {
            s[ni][0] = __expf(fmaf(s[ni][0], scale, -mn0));
            s[ni][1] = __expf(fmaf(s[ni][1], scale, -mn0));
            s[ni][2] = __expf(fmaf(s[ni][2], scale, -mn1));
            s[ni][3] = __expf(fmaf(s[ni][3], scale, -mn1));
            rs0 += s[ni][0] + s[ni][1];
            rs1 += s[ni][2] + s[ni][3];
        }
        rs0 += __shfl_xor_sync(0xffffffffu, rs0, 1);
        rs0 += __shfl_xor_sync(0xffffffffu, rs0, 2);
        rs1 += __shfl_xor_sync(0xffffffffu, rs1, 1);
        rs1 += __shfl_xor_sync(0xffffffffu, rs1, 2);
        l_[0] = l_[0] * a0 + rs0;
        l_[1] = l_[1] * a1 + rs1;

#pragma unroll
        for (int kc = 0; kc < 4; ++kc) {
            uint32_t ph[4], pl[4];
            split2(s[2 * kc][0],     s[2 * kc][1],     ph[0], pl[0]);
            split2(s[2 * kc][2],     s[2 * kc][3],     ph[1], pl[1]);
            split2(s[2 * kc + 1][0], s[2 * kc + 1][1], ph[2], pl[2]);
            split2(s[2 * kc + 1][2], s[2 * kc + 1][3], ph[3], pl[3]);
#pragma unroll
            for (int g = 0; g < 4; ++g) {
                uint32_t voff = SWZ((kc * 16 + lrow) * 128 + (g * 2 + lchk) * 16);
                uint32_t vh[4];
                ldsm_x4_t(vh, st + ST_VH + voff);
                mma16816(o[2 * g],     ph, vh[0], vh[1]);
                mma16816(o[2 * g],     pl, vh[0], vh[1]);
                mma16816(o[2 * g + 1], ph, vh[2], vh[3]);
                mma16816(o[2 * g + 1], pl, vh[2], vh[3]);
            }
        }
        __syncthreads();
    }

    const float inv0 = 1.f / l_[0];
    const float inv1 = 1.f / l_[1];
    const int r0 = q0 + wid * 16 + (lane >> 2);
    const int cb = h * 64 + (lane & 3) * 2;
    const size_t tok = (size_t)b * SQL;
#pragma unroll
    for (int nd = 0; nd < 8; ++nd) {
        int c = cb + nd * 8;
        *(uint32_t*)&g_aoh[(tok + r0) * EMBED + c] =
            pack2(__float2half_rn(o[nd][0] * inv0), __float2half_rn(o[nd][1] * inv0));
        *(uint32_t*)&g_aoh[(tok + r0 + 8) * EMBED + c] =
            pack2(__float2half_rn(o[nd][2] * inv1), __float2half_rn(o[nd][3] * inv1));
    }
}

// ---------------------------------------------------------------------------
// Launch
// ---------------------------------------------------------------------------
extern "C" void kernel_launch(void* const* d_in, const int* in_sizes, int n_in,
                              void* d_out, int out_size)
{
    const float* x   = (const float*)d_in[0];
    const float* ctx = (const float*)d_in[1];
    const float* Wq  = (const float*)d_in[2];
    const float* bq  = (const float*)d_in[3];
    const float* Wk  = (const float*)d_in[4];
    const float* bk  = (const float*)d_in[5];
    const float* Wv  = (const float*)d_in[6];
    const float* bv  = (const float*)d_in[7];
    const float* Wp  = (const float*)d_in[8];
    const float* bp  = (const float*)d_in[9];
    float* out = (float*)d_out;

    __half *xh, *ch_, *Qh, *Kh, *Vh, *aoh, *WqT, *WkT, *WvT, *WpT;
    cudaGetSymbolAddress((void**)&xh,  g_xh);
    cudaGetSymbolAddress((void**)&ch_, g_ch);
    cudaGetSymbolAddress((void**)&Qh,  g_Qh);
    cudaGetSymbolAddress((void**)&Kh,  g_Kh);
    cudaGetSymbolAddress((void**)&Vh,  g_Vh);
    cudaGetSymbolAddress((void**)&aoh, g_aoh);
    cudaGetSymbolAddress((void**)&WqT, g_WqT);
    cudaGetSymbolAddress((void**)&WkT, g_WkT);
    cudaGetSymbolAddress((void**)&WvT, g_WvT);
    cudaGetSymbolAddress((void**)&WpT, g_WpT);

    cudaFuncSetAttribute(gemm_qkv,
                         cudaFuncAttributeMaxDynamicSharedMemorySize, GEMM_SMEM);
    cudaFuncSetAttribute(gemm_out,
                         cudaFuncAttributeMaxDynamicSharedMemorySize, GEMM_SMEM);
    cudaFuncSetAttribute(flash_mma,
                         cudaFuncAttributeMaxDynamicSharedMemorySize, FLASH_SMEM);

    const int NX = NX_ROWS * EMBED;
    const int NC = NC_ROWS * EMBED;

    // Convert activations to fp16
    cvt_f32h<<<(NX / 4 + 255) / 256, 256>>>((const float4*)x,   xh,  NX / 4);
    cvt_f32h<<<(NC / 4 + 255) / 256, 256>>>((const float4*)ctx, ch_, NC / 4);

    // Transpose weights to fp16
    TArgs ta;
    ta.s[0] = {Wq, WqT};
    ta.s[1] = {Wk, WkT};
    ta.s[2] = {Wv, WvT};
    transpose_h3<<<dim3(EMBED / 32, EMBED / 32, 3), dim3(32, 8)>>>(ta, EMBED, EMBED);
    transpose_h<<<dim3(VOCAB / 32, EMBED / 32), dim3(32, 8)>>>(Wp, WpT, EMBED, VOCAB);

    // Fused Q/K/V projections (1-term fp16)
    QKVArgs qa;
    qa.s[0] = {xh,  WqT, bq, Qh};
    qa.s[1] = {ch_, WkT, bk, Kh};
    qa.s[2] = {ch_, WvT, bv, Vh};
    gemm_qkv<<<dim3(EMBED / 128, NC_ROWS / 128, 3), 256, GEMM_SMEM>>>(qa);

    // Flash attention (QK 1-term, PV 2-term with P split)
    flash_mma<<<dim3(SQL / 128, BATCH * NHEADS), 256, FLASH_SMEM>>>();

    // Output projection (1-term fp16)
    gemm_out<<<dim3(VOCAB / 128, NX_ROWS / 128), 256, GEMM_SMEM>>>(
        aoh, WpT, bp, out, VOCAB, EMBED);
}

// round 16
// speedup vs baseline: 4.3987x; 1.2047x over previous
#include <cuda_runtime.h>
#include <cuda_fp16.h>
#include <math.h>
#include <stdint.h>

#define EMBED  1024
#define NHEADS 16
#define HDIM   64
#define VOCAB  4096
#define BATCH  2
#define SQL    1024
#define SKVL   2048

#define NX_ROWS (BATCH * SQL)
#define NC_ROWS (BATCH * SKVL)

// ---------------------------------------------------------------------------
// Scratch (allocation-free __device__ globals)
// ---------------------------------------------------------------------------
__device__ __align__(16) __half g_xh [NX_ROWS * EMBED];
__device__ __align__(16) __half g_ch [NC_ROWS * EMBED];
__device__ __align__(16) __half g_Qh [NX_ROWS * EMBED];
__device__ __align__(16) __half g_Kh [NC_ROWS * EMBED];
__device__ __align__(16) __half g_Vh [NC_ROWS * EMBED];
__device__ __align__(16) __half g_aoh[NX_ROWS * EMBED];
__device__ __align__(16) __half g_Wq16[EMBED * EMBED];   // native [K][N] fp16
__device__ __align__(16) __half g_Wk16[EMBED * EMBED];
__device__ __align__(16) __half g_Wv16[EMBED * EMBED];
__device__ __align__(16) __half g_Wp16[EMBED * VOCAB];

// ---------------------------------------------------------------------------
// Helpers
// ---------------------------------------------------------------------------
__device__ __forceinline__ uint32_t smem_u32(const void* p) {
    uint32_t a;
    asm("{ .reg .u64 t; cvta.to.shared.u64 t, %1; cvt.u32.u64 %0, t; }"
        : "=r"(a) : "l"(p));
    return a;
}
__device__ __forceinline__ void cpasync16(uint32_t dst, const void* src) {
    asm volatile("cp.async.cg.shared.global [%0], [%1], 16;"
                 :: "r"(dst), "l"(src) : "memory");
}
#define CP_COMMIT() asm volatile("cp.async.commit_group;" ::: "memory")
#define CP_WAIT(N)  asm volatile("cp.async.wait_group %0;" :: "n"(N) : "memory")

__device__ __forceinline__ void mma16816(float* c, const uint32_t* a,
                                         uint32_t b0, uint32_t b1) {
    asm volatile(
        "mma.sync.aligned.m16n8k16.row.col.f32.f16.f16.f32 "
        "{%0,%1,%2,%3}, {%4,%5,%6,%7}, {%8,%9}, {%0,%1,%2,%3};"
        : "+f"(c[0]), "+f"(c[1]), "+f"(c[2]), "+f"(c[3])
        : "r"(a[0]), "r"(a[1]), "r"(a[2]), "r"(a[3]), "r"(b0), "r"(b1));
}
__device__ __forceinline__ void ldsm_x4(uint32_t* r, uint32_t addr) {
    asm volatile("ldmatrix.sync.aligned.m8n8.x4.shared.b16 {%0,%1,%2,%3}, [%4];"
                 : "=r"(r[0]), "=r"(r[1]), "=r"(r[2]), "=r"(r[3]) : "r"(addr));
}
__device__ __forceinline__ void ldsm_x4_t(uint32_t* r, uint32_t addr) {
    asm volatile("ldmatrix.sync.aligned.m8n8.x4.trans.shared.b16 {%0,%1,%2,%3}, [%4];"
                 : "=r"(r[0]), "=r"(r[1]), "=r"(r[2]), "=r"(r[3]) : "r"(addr));
}

__device__ __forceinline__ uint32_t pack2(__half a, __half b) {
    __half2 t = __halves2half2(a, b);
    return *(uint32_t*)&t;
}
__device__ __forceinline__ void split2(float a, float b, uint32_t& h, uint32_t& l) {
    __half ha = __float2half_rn(a), hb = __float2half_rn(b);
    __half la = __float2half_rn(a - __half2float(ha));
    __half lb = __float2half_rn(b - __half2float(hb));
    h = pack2(ha, hb);
    l = pack2(la, lb);
}

#define SWZ(off) ((uint32_t)(off) ^ ((((uint32_t)(off)) >> 3) & 0x70u))

// ---------------------------------------------------------------------------
// Fused fp32 -> fp16 convert: grid.z selects segment
// ---------------------------------------------------------------------------
struct CvtSeg { const float4* in; __half* out; int n4; };
struct CvtArgs { CvtSeg s[6]; };

__global__ __launch_bounds__(256) void cvt_all(CvtArgs a)
{
    const CvtSeg& s = a.s[blockIdx.z];
    int i = blockIdx.x * 256 + threadIdx.x;
    if (i >= s.n4) return;
    float4 v = s.in[i];
    __half h[4] = {__float2half_rn(v.x), __float2half_rn(v.y),
                   __float2half_rn(v.z), __float2half_rn(v.w)};
    *(uint2*)&s.out[i * 4] = *(uint2*)h;
}

// ---------------------------------------------------------------------------
// fp16 GEMM (1-term): C = A @ W + bias, W native [K][N] fp16.
// A: K-major rows, non-trans ldmatrix (80B pitch).
// W(B): contraction-major rows, trans ldmatrix (flash-PV-proven pattern).
// B smem tile: [nh=2][k=32][64 halves] = 64 rows x 128B, SWZ per row.
// CTA 128x128, k-tile 32, 256 thr (8 warps 2m x 4n, warp 64x32), dbl buffer.
// ---------------------------------------------------------------------------
#define PITCH_A   80
#define A_TILE_B  (128 * PITCH_A)         // 10240
#define OFF_A     0
#define OFF_B     A_TILE_B                // 10240 (1024-aligned: 10*1024)
#define B_TILE_B  (64 * 128)              // 8192
#define BUF_B     (A_TILE_B + B_TILE_B)   // 18432
#define GEMM_SMEM (2 * BUF_B)             // 36864

__device__ __forceinline__ void gemm_core(
    const __half* __restrict__ Ah, const __half* __restrict__ W16,
    const float* __restrict__ bias, float* __restrict__ Cf,
    __half* __restrict__ Ch, int N, int K, char* smem)
{
    const uint32_t sbase = smem_u32(smem);

    const int tid  = threadIdx.x;
    const int wid  = tid >> 5;
    const int lane = tid & 31;
    const int wm   = wid & 1;
    const int wn   = wid >> 1;
    const int lr   = lane >> 2;
    const int lc   = lane & 3;

    const int m0 = blockIdx.y * 128;
    const int n0 = blockIdx.x * 128;

    const size_t aBase = (size_t)m0 * K;

    auto load_tile = [&](int buf, int kt) {
        uint32_t sp = sbase + buf * BUF_B;
        const size_t gk = (size_t)kt * 32;
        // A: 128 rows x 64B (4 chunks), 512 chunks, 2/thread
#pragma unroll
        for (int j = 0; j < 2; ++j) {
            int row = (tid >> 2) + j * 64;
            int cc  = tid & 3;
            uint32_t so = (uint32_t)(row * PITCH_A + cc * 16);
            cpasync16(sp + OFF_A + so, Ah + aBase + (size_t)row * K + gk + cc * 8);
        }
        // B(W): 32 k-rows x 128 n, 512 chunks, 2/thread
#pragma unroll
        for (int j = 0; j < 2; ++j) {
            int idx = tid + j * 256;
            int k  = idx >> 4;        // 0..31
            int nc = idx & 15;        // 16 chunks of 8 n
            int nh = nc >> 3;
            uint32_t so = SWZ((uint32_t)((nh * 32 + k) * 128 + (nc & 7) * 16));
            cpasync16(sp + OFF_B + so,
                      W16 + (gk + k) * (size_t)N + n0 + nc * 8);
        }
        CP_COMMIT();
    };

    float acc[4][4][4];
#pragma unroll
    for (int i = 0; i < 4; ++i)
#pragma unroll
        for (int j = 0; j < 4; ++j)
#pragma unroll
            for (int r = 0; r < 4; ++r) acc[i][j][r] = 0.f;

    const int lrow = lane & 15;
    const int lchk = lane >> 4;
    const uint32_t aOff = (uint32_t)((wm * 64 + lrow) * PITCH_A + lchk * 16);
    // B: rows = (wn>>1)*32 + ks*16 + lrow ; cols byte = (wn&1)*64 + gg*32 + lchk*16
    const uint32_t bRowBase = (uint32_t)((wn >> 1) * 32 + lrow);
    const uint32_t bColByte = (uint32_t)((wn & 1) * 64 + lchk * 16);

    load_tile(0, 0);

    const int nk = K >> 5;
    for (int kt = 0; kt < nk; ++kt) {
        const int cur = kt & 1;
        if (kt + 1 < nk) { load_tile(cur ^ 1, kt + 1); CP_WAIT(1); }
        else             { CP_WAIT(0); }
        __syncthreads();

        const uint32_t sA = sbase + cur * BUF_B + OFF_A;
        const uint32_t sB = sbase + cur * BUF_B + OFF_B;

#pragma unroll
        for (int ks = 0; ks < 2; ++ks) {
            uint32_t ah[4][4];
#pragma unroll
            for (int mi = 0; mi < 4; ++mi)
                ldsm_x4(ah[mi], sA + aOff + mi * (16 * PITCH_A) + ks * 32);

#pragma unroll
            for (int gg = 0; gg < 2; ++gg) {
                uint32_t bt[4];
                uint32_t boff = SWZ((bRowBase + ks * 16) * 128
                                    + bColByte + gg * 32);
                ldsm_x4_t(bt, sB + boff);
#pragma unroll
                for (int mi = 0; mi < 4; ++mi) {
                    mma16816(acc[mi][2 * gg],     ah[mi], bt[0], bt[1]);
                    mma16816(acc[mi][2 * gg + 1], ah[mi], bt[2], bt[3]);
                }
            }
        }
        __syncthreads();
    }

#pragma unroll
    for (int mi = 0; mi < 4; ++mi) {
        int r = m0 + wm * 64 + mi * 16 + lr;
#pragma unroll
        for (int ni = 0; ni < 4; ++ni) {
            int c = n0 + wn * 32 + ni * 8 + lc * 2;
            float b0 = __ldg(bias + c), b1 = __ldg(bias + c + 1);
            float v00 = acc[mi][ni][0] + b0, v01 = acc[mi][ni][1] + b1;
            float v10 = acc[mi][ni][2] + b0, v11 = acc[mi][ni][3] + b1;
            if (Cf) {
                *(float2*)&Cf[(size_t)r * N + c]       = make_float2(v00, v01);
                *(float2*)&Cf[(size_t)(r + 8) * N + c] = make_float2(v10, v11);
            } else {
                *(uint32_t*)&Ch[(size_t)r * N + c] =
                    pack2(__float2half_rn(v00), __float2half_rn(v01));
                *(uint32_t*)&Ch[(size_t)(r + 8) * N + c] =
                    pack2(__float2half_rn(v10), __float2half_rn(v11));
            }
        }
    }
}

__global__ __launch_bounds__(256, 2) void gemm_out(
    const __half* Ah, const __half* W16,
    const float* bias, float* C, int N, int K)
{
    extern __shared__ char smem[];
    gemm_core(Ah, W16, bias, C, nullptr, N, K, smem);
}

struct GSet {
    const __half *Ah, *W16;
    const float* bias;
    __half *Ch;
};
struct QKVArgs { GSet s[3]; };

__global__ __launch_bounds__(256, 2) void gemm_qkv(QKVArgs a)
{
    extern __shared__ char smem[];
    if (blockIdx.z == 0 && blockIdx.y >= NX_ROWS / 128) return;
    const GSet& s = a.s[blockIdx.z];
    gemm_core(s.Ah, s.W16, s.bias, nullptr, s.Ch, EMBED, EMBED, smem);
}

// ---------------------------------------------------------------------------
// Flash attention: QK^T 1-term; PV 2-term (P split, V single).
// Now pinned at 2 CTAs/SM -> single wave + exp/MMA cross-CTA overlap.
// ---------------------------------------------------------------------------
#define FSM_QH   0
#define FSM_ST   16384
#define ST_KH    0
#define ST_VH    8192
#define ST_SZ    16384
#define FLASH_SMEM (FSM_ST + 2 * ST_SZ)   // 49152 B

__global__ __launch_bounds__(256, 2) void flash_mma()
{
    extern __shared__ char sm[];
    const uint32_t sb = smem_u32(sm);

    const int tid  = threadIdx.x;
    const int wid  = tid >> 5;
    const int lane = tid & 31;
    const int b    = blockIdx.y >> 4;
    const int h    = blockIdx.y & 15;
    const int q0   = blockIdx.x * 128;

    {
        const size_t qtok = (size_t)(b * SQL + q0);
#pragma unroll
        for (int i = 0; i < 4; ++i) {
            int idx = i * 256 + tid;
            int r = idx >> 3, cc = idx & 7;
            uint32_t off = SWZ(r * 128 + cc * 16);
            cpasync16(sb + FSM_QH + off, g_Qh + (qtok + r) * EMBED + h * 64 + cc * 8);
        }
    }
    auto load_kv = [&](int buf, int kb) {
        uint32_t st = sb + FSM_ST + buf * ST_SZ;
        const size_t tok = (size_t)(b * SKVL + kb * 64);
#pragma unroll
        for (int i = 0; i < 2; ++i) {
            int idx = i * 256 + tid;
            int r = idx >> 3, cc = idx & 7;
            uint32_t off = SWZ(r * 128 + cc * 16);
            size_t g = (tok + r) * EMBED + h * 64 + cc * 8;
            cpasync16(st + ST_KH + off, g_Kh + g);
            cpasync16(st + ST_VH + off, g_Vh + g);
        }
    };
    load_kv(0, 0);
    CP_COMMIT();

    float m_[2] = {-1e30f, -1e30f};
    float l_[2] = {0.f, 0.f};
    float o[8][4];
#pragma unroll
    for (int i = 0; i < 8; ++i)
#pragma unroll
        for (int j = 0; j < 4; ++j) o[i][j] = 0.f;

    const int lrow = lane & 15;
    const int lchk = lane >> 4;
    const float scale = 0.125f;

    const int NCH = SKVL / 64;
    for (int ch = 0; ch < NCH; ++ch) {
        const int cur = ch & 1;
        if (ch + 1 < NCH) { load_kv(cur ^ 1, ch + 1); CP_COMMIT(); CP_WAIT(1); }
        else              { CP_WAIT(0); }
        __syncthreads();

        const uint32_t st = sb + FSM_ST + cur * ST_SZ;

        float s[8][4];
#pragma unroll
        for (int i = 0; i < 8; ++i)
#pragma unroll
            for (int j = 0; j < 4; ++j) s[i][j] = 0.f;

#pragma unroll
        for (int kk = 0; kk < 4; ++kk) {
            uint32_t qoff = SWZ((wid * 16 + lrow) * 128 + (kk * 2 + lchk) * 16);
            uint32_t qh[4];
            ldsm_x4(qh, sb + FSM_QH + qoff);
#pragma unroll
            for (int cg = 0; cg < 4; ++cg) {
                uint32_t koff = SWZ((cg * 16 + lrow) * 128 + (kk * 2 + lchk) * 16);
                uint32_t kh[4];
                ldsm_x4(kh, st + ST_KH + koff);
                mma16816(s[2 * cg],     qh, kh[0], kh[2]);
                mma16816(s[2 * cg + 1], qh, kh[1], kh[3]);
            }
        }

        float rm0 = -1e30f, rm1 = -1e30f;
#pragma unroll
        for (int ni = 0; ni < 8; ++ni) {
            rm0 = fmaxf(rm0, fmaxf(s[ni][0], s[ni][1]));
            rm1 = fmaxf(rm1, fmaxf(s[ni][2], s[ni][3]));
        }
        rm0 = fmaxf(rm0, __shfl_xor_sync(0xffffffffu, rm0, 1));
        rm0 = fmaxf(rm0, __shfl_xor_sync(0xffffffffu, rm0, 2));
        rm1 = fmaxf(rm1, __shfl_xor_sync(0xffffffffu, rm1, 1));
        rm1 = fmaxf(rm1, __shfl_xor_sync(0xffffffffu, rm1, 2));

        float mn0 = fmaxf(m_[0], rm0 * scale);
        float mn1 = fmaxf(m_[1], rm1 * scale);
        float a0 = __expf(m_[0] - mn0);
        float a1 = __expf(m_[1] - mn1);
        m_[0] = mn0; m_[1] = mn1;
#pragma unroll
        for (int nd = 0; nd < 8; ++nd) {
            o[nd][0] *= a0; o[nd][1] *= a0;
            o[nd][2] *= a1; o[nd][3] *= a1;
        }
        float rs0 = 0.f, rs1 = 0.f;
#pragma unroll
        for (int ni = 0; ni < 8; ++ni) {
            s[ni][0] = __expf(fmaf(s[ni][0], scale, -mn0));
            s[ni][1] = __expf(fmaf(s[ni][1], scale, -mn0));
            s[ni][2] = __expf(fmaf(s[ni][2], scale, -mn1));
            s[ni][3] = __expf(fmaf(s[ni][3], scale, -mn1));
            rs0 += s[ni][0] + s[ni][1];
            rs1 += s[ni][2] + s[ni][3];
        }
        rs0 += __shfl_xor_sync(0xffffffffu, rs0, 1);
        rs0 += __shfl_xor_sync(0xffffffffu, rs0, 2);
        rs1 += __shfl_xor_sync(0xffffffffu, rs1, 1);
        rs1 += __shfl_xor_sync(0xffffffffu, rs1, 2);
        l_[0] = l_[0] * a0 + rs0;
        l_[1] = l_[1] * a1 + rs1;

#pragma unroll
        for (int kc = 0; kc < 4; ++kc) {
            uint32_t ph[4], pl[4];
            split2(s[2 * kc][0],     s[2 * kc][1],     ph[0], pl[0]);
            split2(s[2 * kc][2],     s[2 * kc][3],     ph[1], pl[1]);
            split2(s[2 * kc + 1][0], s[2 * kc + 1][1], ph[2], pl[2]);
            split2(s[2 * kc + 1][2], s[2 * kc + 1][3], ph[3], pl[3]);
#pragma unroll
            for (int g = 0; g < 4; ++g) {
                uint32_t voff = SWZ((kc * 16 + lrow) * 128 + (g * 2 + lchk) * 16);
                uint32_t vh[4];
                ldsm_x4_t(vh, st + ST_VH + voff);
                mma16816(o[2 * g],     ph, vh[0], vh[1]);
                mma16816(o[2 * g],     pl, vh[0], vh[1]);
                mma16816(o[2 * g + 1], ph, vh[2], vh[3]);
                mma16816(o[2 * g + 1], pl, vh[2], vh[3]);
            }
        }
        __syncthreads();
    }

    const float inv0 = 1.f / l_[0];
    const float inv1 = 1.f / l_[1];
    const int r0 = q0 + wid * 16 + (lane >> 2);
    const int cb = h * 64 + (lane & 3) * 2;
    const size_t tok = (size_t)b * SQL;
#pragma unroll
    for (int nd = 0; nd < 8; ++nd) {
        int c = cb + nd * 8;
        *(uint32_t*)&g_aoh[(tok + r0) * EMBED + c] =
            pack2(__float2half_rn(o[nd][0] * inv0), __float2half_rn(o[nd][1] * inv0));
        *(uint32_t*)&g_aoh[(tok + r0 + 8) * EMBED + c] =
            pack2(__float2half_rn(o[nd][2] * inv1), __float2half_rn(o[nd][3] * inv1));
    }
}

// ---------------------------------------------------------------------------
// Launch
// ---------------------------------------------------------------------------
extern "C" void kernel_launch(void* const* d_in, const int* in_sizes, int n_in,
                              void* d_out, int out_size)
{
    const float* x   = (const float*)d_in[0];
    const float* ctx = (const float*)d_in[1];
    const float* Wq  = (const float*)d_in[2];
    const float* bq  = (const float*)d_in[3];
    const float* Wk  = (const float*)d_in[4];
    const float* bk  = (const float*)d_in[5];
    const float* Wv  = (const float*)d_in[6];
    const float* bv  = (const float*)d_in[7];
    const float* Wp  = (const float*)d_in[8];
    const float* bp  = (const float*)d_in[9];
    float* out = (float*)d_out;

    __half *xh, *ch_, *Qh, *Kh, *Vh, *aoh, *Wq16, *Wk16, *Wv16, *Wp16;
    cudaGetSymbolAddress((void**)&xh,   g_xh);
    cudaGetSymbolAddress((void**)&ch_,  g_ch);
    cudaGetSymbolAddress((void**)&Qh,   g_Qh);
    cudaGetSymbolAddress((void**)&Kh,   g_Kh);
    cudaGetSymbolAddress((void**)&Vh,   g_Vh);
    cudaGetSymbolAddress((void**)&aoh,  g_aoh);
    cudaGetSymbolAddress((void**)&Wq16, g_Wq16);
    cudaGetSymbolAddress((void**)&Wk16, g_Wk16);
    cudaGetSymbolAddress((void**)&Wv16, g_Wv16);
    cudaGetSymbolAddress((void**)&Wp16, g_Wp16);

    cudaFuncSetAttribute(gemm_qkv,
                         cudaFuncAttributeMaxDynamicSharedMemorySize, GEMM_SMEM);
    cudaFuncSetAttribute(gemm_out,
                         cudaFuncAttributeMaxDynamicSharedMemorySize, GEMM_SMEM);
    cudaFuncSetAttribute(flash_mma,
                         cudaFuncAttributeMaxDynamicSharedMemorySize, FLASH_SMEM);

    const int NX = NX_ROWS * EMBED;          // 2,097,152
    const int NC = NC_ROWS * EMBED;          // 4,194,304
    const int NW = EMBED * EMBED;            // 1,048,576
    const int NP = EMBED * VOCAB;            // 4,194,304

    // One fused convert for everything (native layouts, no transpose)
    CvtArgs ca;
    ca.s[0] = {(const float4*)x,   xh,   NX / 4};
    ca.s[1] = {(const float4*)ctx, ch_,  NC / 4};
    ca.s[2] = {(const float4*)Wq,  Wq16, NW / 4};
    ca.s[3] = {(const float4*)Wk,  Wk16, NW / 4};
    ca.s[4] = {(const float4*)Wv,  Wv16, NW / 4};
    ca.s[5] = {(const float4*)Wp,  Wp16, NP / 4};
    cvt_all<<<dim3((NC / 4 + 255) / 256, 1, 6), 256>>>(ca);

    // Fused Q/K/V projections (1-term fp16, W native layout)
    QKVArgs qa;
    qa.s[0] = {xh,  Wq16, bq, Qh};
    qa.s[1] = {ch_, Wk16, bk, Kh};
    qa.s[2] = {ch_, Wv16, bv, Vh};
    gemm_qkv<<<dim3(EMBED / 128, NC_ROWS / 128, 3), 256, GEMM_SMEM>>>(qa);

    // Flash attention (single wave, 2 CTAs/SM)
    flash_mma<<<dim3(SQL / 128, BATCH * NHEADS), 256, FLASH_SMEM>>>();

    // Output projection
    gemm_out<<<dim3(VOCAB / 128, NX_ROWS / 128), 256, GEMM_SMEM>>>(
        aoh, Wp16, bp, out, VOCAB, EMBED);
}